// round 13
// baseline (speedup 1.0000x reference)
#include <cuda_runtime.h>
#include <cstdint>
#include <math.h>

#define DIMC   768
#define NHEADS 12
#define HDIM   64
#define BATCH  8
#define SEQ    1024
#define MROWS  (BATCH*SEQ)
#define PAIRS  (BATCH*NHEADS)
#define ATT_SCALE 0.125f

// ---------------- scratch (static device memory; no cudaMalloc allowed) ----
// sigma16 k-permutation on GEMM k-dims (g_Xr/g_Wq/g_Wp/g_O, and Q/K d-dim).
// g_Vf: FRAGMENT-MAJOR V: [pair][G(128)][p(4)][lane(32)] float4 =
//   { V[G*8+2q][p*8+r], V[G*8+2q+1][p*8+r], V[G*8+2q][(p+4)*8+r], V[G*8+2q+1][(p+4)*8+r] }
//   (lane = r*4+q). One LDS.128 = b-frags for od[p] AND od[p+4].
__device__ __align__(16) float g_Q   [(size_t)PAIRS*SEQ*HDIM];
__device__ __align__(16) float g_K   [(size_t)PAIRS*SEQ*HDIM];
__device__ __align__(16) float g_Vf  [(size_t)PAIRS*SEQ*HDIM];
__device__ __align__(16) float g_O   [(size_t)MROWS*DIMC];
__device__ __align__(16) float g_Msig[(size_t)NHEADS*SEQ*SEQ];
__device__ __align__(16) float g_Xr  [(size_t)MROWS*DIMC];
__device__ __align__(16) float g_Wq  [(size_t)3*DIMC*DIMC];
__device__ __align__(16) float g_Wp  [(size_t)DIMC*DIMC];

// ======================= helpers ===========================================
__device__ __forceinline__ uint32_t cvt_tf32(float x) {
    uint32_t r; asm("cvt.rna.tf32.f32 %0, %1;" : "=r"(r) : "f"(x)); return r;
}
__device__ __forceinline__ float tf32f(float x) {
    return __uint_as_float(cvt_tf32(x));
}
__device__ __forceinline__ int sig16(int j) {
    int jj = j & 15, jjj = jj & 7;
    return (j & ~15) + (jjj & 3) * 4 + (jj >> 3) * 2 + (jjj >> 2);
}
__device__ __forceinline__ void mma_tf32(float (&c)[4], const uint32_t (&a)[4],
                                         const uint32_t (&b)[2]) {
    asm volatile("mma.sync.aligned.m16n8k8.row.col.f32.tf32.tf32.f32 "
                 "{%0,%1,%2,%3}, {%4,%5,%6,%7}, {%8,%9}, {%0,%1,%2,%3};"
                 : "+f"(c[0]), "+f"(c[1]), "+f"(c[2]), "+f"(c[3])
                 : "r"(a[0]), "r"(a[1]), "r"(a[2]), "r"(a[3]),
                   "r"(b[0]), "r"(b[1]));
}
__device__ __forceinline__ uint32_t smem_u32(const void* p) {
    uint32_t a;
    asm("{ .reg .u64 t; cvta.to.shared.u64 t, %1; cvt.u32.u64 %0, t; }"
        : "=r"(a) : "l"(p));
    return a;
}
#define CP_ASYNC16(dst, src) \
    asm volatile("cp.async.cg.shared.global [%0], [%1], 16;" \
                 :: "r"(dst), "l"(src) : "memory")
#define CP_COMMIT() asm volatile("cp.async.commit_group;" ::: "memory")
#define CP_WAIT(n)  asm volatile("cp.async.wait_group %0;" :: "n"(n) : "memory")

// ============================================================================
// Pre-kernels: fused tf32 round + sigma16 permutation; presig
// ============================================================================
#define NB_X  (MROWS * DIMC / 1024)
#define NB_WQ (3 * DIMC * DIMC / 1024)
#define NB_WP (DIMC * DIMC / 1024)

__device__ __forceinline__ void round_perm_elem(const float* __restrict__ src,
                                                float* __restrict__ dst,
                                                size_t i) {
    float4 v = *reinterpret_cast<const float4*>(src + i);
    int col = (int)(i % DIMC);
    size_t rowbase = i - col;
    int off = ((col >> 3) & 1) * 2 + ((col >> 2) & 1);
    size_t d0 = rowbase + (col & ~15) + off;
    dst[d0]      = tf32f(v.x);
    dst[d0 + 4]  = tf32f(v.y);
    dst[d0 + 8]  = tf32f(v.z);
    dst[d0 + 12] = tf32f(v.w);
}

__global__ __launch_bounds__(256) void round_all(const float* __restrict__ x,
                                                 const float* __restrict__ wq,
                                                 const float* __restrict__ wp) {
    int blk = blockIdx.x;
    if (blk < NB_X) {
        round_perm_elem(x, g_Xr, ((size_t)blk * 256 + threadIdx.x) * 4);
    } else if (blk < NB_X + NB_WQ) {
        round_perm_elem(wq, g_Wq, ((size_t)(blk - NB_X) * 256 + threadIdx.x) * 4);
    } else {
        round_perm_elem(wp, g_Wp, ((size_t)(blk - NB_X - NB_WQ) * 256 + threadIdx.x) * 4);
    }
}

__global__ __launch_bounds__(256) void presig(const float* __restrict__ m) {
    size_t i = ((size_t)blockIdx.x * 256 + threadIdx.x) * 4;
    float4 v = *reinterpret_cast<const float4*>(m + i);
    float4 o;
    o.x = ATT_SCALE / (1.f + __expf(-v.x));
    o.y = ATT_SCALE / (1.f + __expf(-v.y));
    o.z = ATT_SCALE / (1.f + __expf(-v.z));
    o.w = ATT_SCALE / (1.f + __expf(-v.w));
    *reinterpret_cast<float4*>(g_Msig + i) = o;
}

// ============================================================================
// NT GEMM core v4 (unchanged): cp.async 2-stage, LDK=48, all-LDS.128 frags
// ============================================================================
#define LDK 48

template <int BN, int NC, int MF, int NF, int WMDIV>
__device__ __forceinline__ void gemm_core(const float* __restrict__ A, int lda,
                                          const float* __restrict__ B, int ldb,
                                          float (&acc)[MF][NF][4],
                                          float* smem) {
    float* As[2] = { smem, smem + 128 * LDK };
    float* Bs[2] = { smem + 2 * 128 * LDK, smem + 2 * 128 * LDK + BN * LDK };

    const int tid  = threadIdx.x;
    const int lane = tid & 31;
    const int wid  = tid >> 5;
    const int wm   = wid % WMDIV;
    const int wn   = wid / WMDIV;
    const int mrow0 = wm * (MF * 16);
    const int ncol0 = wn * (NF * 8);
    const int r = lane >> 2, q = lane & 3;

#pragma unroll
    for (int mf = 0; mf < MF; mf++)
#pragma unroll
        for (int nf = 0; nf < NF; nf++)
#pragma unroll
            for (int i = 0; i < 4; i++) acc[mf][nf][i] = 0.f;

    const int arow = tid >> 3, ac = (tid & 7) * 4;

    auto copy = [&](int i, int buf) {
        int k0 = i * 32;
#pragma unroll
        for (int p = 0; p < 4; p++) {
            int row = arow + p * 32;
            CP_ASYNC16(smem_u32(&As[buf][row * LDK + ac]),
                       A + (size_t)row * lda + k0 + ac);
        }
#pragma unroll
        for (int p = 0; p < BN / 32; p++) {
            int row = arow + p * 32;
            CP_ASYNC16(smem_u32(&Bs[buf][row * LDK + ac]),
                       B + (size_t)row * ldb + k0 + ac);
        }
    };

    copy(0, 0); CP_COMMIT();
    copy(1, 1); CP_COMMIT();
    CP_WAIT(1);
    __syncthreads();

#pragma unroll 1
    for (int i = 0; i < NC; i++) {
        const int buf = i & 1;
        const float* Ab = As[buf];
        const float* Bb = Bs[buf];
#pragma unroll
        for (int blk = 0; blk < 2; blk++) {
            uint32_t af[MF][2][4], bf[NF][2][2];
#pragma unroll
            for (int mf = 0; mf < MF; mf++) {
                const float* ap = &Ab[(mrow0 + mf * 16 + r) * LDK + blk * 16 + 4 * q];
                float4 a0 = *reinterpret_cast<const float4*>(ap);
                float4 a1 = *reinterpret_cast<const float4*>(ap + 8 * LDK);
                af[mf][0][0] = __float_as_uint(a0.x); af[mf][0][1] = __float_as_uint(a1.x);
                af[mf][0][2] = __float_as_uint(a0.y); af[mf][0][3] = __float_as_uint(a1.y);
                af[mf][1][0] = __float_as_uint(a0.z); af[mf][1][1] = __float_as_uint(a1.z);
                af[mf][1][2] = __float_as_uint(a0.w); af[mf][1][3] = __float_as_uint(a1.w);
            }
#pragma unroll
            for (int nf = 0; nf < NF; nf++) {
                float4 b = *reinterpret_cast<const float4*>(
                    &Bb[(ncol0 + nf * 8 + r) * LDK + blk * 16 + 4 * q]);
                bf[nf][0][0] = __float_as_uint(b.x); bf[nf][0][1] = __float_as_uint(b.y);
                bf[nf][1][0] = __float_as_uint(b.z); bf[nf][1][1] = __float_as_uint(b.w);
            }
#pragma unroll
            for (int mf = 0; mf < MF; mf++)
#pragma unroll
                for (int nf = 0; nf < NF; nf++) {
                    mma_tf32(acc[mf][nf], af[mf][0], bf[nf][0]);
                    mma_tf32(acc[mf][nf], af[mf][1], bf[nf][1]);
                }
        }
        if (i == NC - 1) break;
        __syncthreads();
        if (i + 2 < NC) { copy(i + 2, buf); CP_COMMIT(); CP_WAIT(1); }
        else            { CP_WAIT(0); }
        __syncthreads();
    }
}

// ============================================================================
// Kernel 1: QKV projection + scatter. Q/K: d-sigma16. V: fragment-major g_Vf.
// ============================================================================
__global__ __launch_bounds__(256) void qkv_tc() {
    extern __shared__ float smf[];
    float acc[4][4][4];
    int brow = blockIdx.y * 128, bcol = blockIdx.x * 128;
    gemm_core<128, 24, 4, 4, 2>(g_Xr + (size_t)brow * DIMC, DIMC,
                                g_Wq + (size_t)bcol * DIMC, DIMC, acc, smf);
    int lane = threadIdx.x & 31, wid = threadIdx.x >> 5;
    int wm = wid % 2, wn = wid / 2, r = lane >> 2, q = lane & 3;
    int part = bcol / 768, rem0 = bcol - part * 768;

#pragma unroll
    for (int mf = 0; mf < 4; mf++)
#pragma unroll
        for (int nf = 0; nf < 4; nf++) {
            int col = rem0 + wn * 32 + nf * 8 + 2 * q;
            int h = col >> 6, d = col & 63;
            int s0 = sig16(d), s1 = sig16(d + 1);
#pragma unroll
            for (int rr = 0; rr < 2; rr++) {
                int m = brow + wm * 64 + mf * 16 + r + rr * 8;
                int b = m >> 10, nq = m & 1023;
                float v0 = tf32f(acc[mf][nf][rr * 2 + 0]);
                float v1 = tf32f(acc[mf][nf][rr * 2 + 1]);
                int pairIdx = b * NHEADS + h;
                if (part < 2) {
                    float* dst = (part == 0) ? g_Q : g_K;
                    size_t base = ((size_t)pairIdx * SEQ + nq) * HDIM;
                    dst[base + s0] = v0;
                    dst[base + s1] = v1;
                } else {
                    // fragment-major V: key=nq, channels d, d+1
                    int G  = nq >> 3;
                    int qq = (nq & 7) >> 1;
                    int e  = nq & 1;
                    size_t gbase = (((size_t)pairIdx * 128 + G) * 4) * 128; // *32 lanes *4 floats
                    {   // d
                        int nfv = d >> 3, rr2 = d & 7;
                        size_t off = gbase + (size_t)(nfv & 3) * 128
                                   + (size_t)(rr2 * 4 + qq) * 4 + (nfv >> 2) * 2 + e;
                        g_Vf[off] = v0;
                    }
                    {   // d+1
                        int d1 = d + 1;
                        int nfv = d1 >> 3, rr2 = d1 & 7;
                        size_t off = gbase + (size_t)(nfv & 3) * 128
                                   + (size_t)(rr2 * 4 + qq) * 4 + (nfv >> 2) * 2 + e;
                        g_Vf[off] = v1;
                    }
                }
            }
        }
}

// ============================================================================
// Kernel 2: FUSED flash attention.
//  - K: smem stride 80, LDS.128 frags (sigma16 d-dim)
//  - V: fragment-major, ONE LDS.128 per (group, p) feeds od[p] and od[p+4]
//  - 3-stage cp.async ring (110592 B, 2 CTAs/SM), 1 syncthreads/iter
//  - group-streamed no-max softmax, P in registers
// ============================================================================
#define KT 64
#define LDTK 80
#define VF_STAGE 4096                        // 8 groups * 4 * 32 lanes * 4 floats
#define NITER (SEQ / KT)
#define STAGE_F (64 * LDTK + VF_STAGE)       // 9216 floats

__global__ __launch_bounds__(256, 2) void flash_tc() {
    extern __shared__ float sm[];

    const int tid = threadIdx.x, lane = tid & 31, wid = tid >> 5;
    const int r = lane >> 2, q = lane & 3;
    const int pair = blockIdx.x;
    const int h = pair % NHEADS, b = pair / NHEADS;
    const int q0 = blockIdx.y * 128;

    const float* Qg = g_Q  + (size_t)pair * SEQ * HDIM;
    const float* Kg = g_K  + (size_t)pair * SEQ * HDIM;
    const float* Vg = g_Vf + (size_t)pair * SEQ * HDIM;   // fragment-major base
    const float* Mg = g_Msig + (size_t)h * SEQ * SEQ;

    const int crow = tid >> 4, cc = (tid & 15) * 4;

    auto copyKV = [&](int kb, int buf) {
        float* Kd = sm + buf * STAGE_F;
        float* Vd = Kd + 64 * LDTK;
        const float* Ksrc = Kg + (size_t)(kb * KT) * HDIM;
        const float* Vsrc = Vg + (size_t)kb * VF_STAGE;   // contiguous 16 KB
#pragma unroll
        for (int p = 0; p < 4; p++) {
            int row = crow + p * 16;
            CP_ASYNC16(smem_u32(&Kd[row * LDTK + cc]), Ksrc + (size_t)row * HDIM + cc);
            int j = tid + p * 256;                        // 1024 float4 chunks
            CP_ASYNC16(smem_u32(&Vd[j * 4]), Vsrc + (size_t)j * 4);
        }
    };

    copyKV(0, 0); CP_COMMIT();
    copyKV(1, 1); CP_COMMIT();

    // ---- Q fragments via LDG.128 from sigma16-permuted global ----
    uint32_t qa[8][4];
    {
        const float* qr0 = Qg + (size_t)(q0 + wid * 16 + r) * HDIM + 4 * q;
        const float* qr1 = qr0 + 8 * HDIM;
#pragma unroll
        for (int blk = 0; blk < 4; blk++) {
            float4 v0 = *reinterpret_cast<const float4*>(qr0 + blk * 16);
            float4 v1 = *reinterpret_cast<const float4*>(qr1 + blk * 16);
            qa[2 * blk][0]     = __float_as_uint(v0.x);
            qa[2 * blk][1]     = __float_as_uint(v1.x);
            qa[2 * blk][2]     = __float_as_uint(v0.y);
            qa[2 * blk][3]     = __float_as_uint(v1.y);
            qa[2 * blk + 1][0] = __float_as_uint(v0.z);
            qa[2 * blk + 1][1] = __float_as_uint(v1.z);
            qa[2 * blk + 1][2] = __float_as_uint(v0.w);
            qa[2 * blk + 1][3] = __float_as_uint(v1.w);
        }
    }

    float od[8][4];
#pragma unroll
    for (int nf = 0; nf < 8; nf++)
#pragma unroll
        for (int i = 0; i < 4; i++) od[nf][i] = 0.f;
    float l0 = 0.f, l1 = 0.f;

    const int row_s0 = q0 + wid * 16 + r;
    const float* Mrow0 = Mg + (size_t)row_s0 * SEQ + 2 * q;
    const float* Mrow1 = Mrow0 + 8 * SEQ;

#pragma unroll 1
    for (int kb = 0; kb < NITER; kb++) {
        if (kb == NITER - 1) { CP_WAIT(0); } else { CP_WAIT(1); }
        __syncthreads();                 // stage kb visible; compute kb-1 done
        if (kb + 2 < NITER) {
            copyKV(kb + 2, (kb + 2) % 3);
            CP_COMMIT();
        }

        const float* Ks = sm + (kb % 3) * STAGE_F;
        const float* Vs = Ks + 64 * LDTK;

        // ---- stream key-groups: S (LDS.128 K, 2 chains) -> exp -> PV --------
#pragma unroll
        for (int g = 0; g < 8; g++) {
            float sa[4] = {0.f, 0.f, 0.f, 0.f};
            float sb[4] = {0.f, 0.f, 0.f, 0.f};
            const float* Kr = &Ks[(g * 8 + r) * LDTK + 4 * q];
#pragma unroll
            for (int blk = 0; blk < 4; blk++) {
                float4 kv = *reinterpret_cast<const float4*>(Kr + blk * 16);
                uint32_t bf0[2] = { __float_as_uint(kv.x), __float_as_uint(kv.y) };
                uint32_t bf1[2] = { __float_as_uint(kv.z), __float_as_uint(kv.w) };
                mma_tf32(sa, qa[2 * blk],     bf0);
                mma_tf32(sb, qa[2 * blk + 1], bf1);
            }
            sa[0] += sb[0]; sa[1] += sb[1]; sa[2] += sb[2]; sa[3] += sb[3];

            int col = kb * KT + g * 8;
            float2 g0 = *reinterpret_cast<const float2*>(Mrow0 + col);
            float2 g1 = *reinterpret_cast<const float2*>(Mrow1 + col);
            float p00 = __expf(sa[0] * g0.x);
            float p01 = __expf(sa[1] * g0.y);
            float p10 = __expf(sa[2] * g1.x);
            float p11 = __expf(sa[3] * g1.y);
            l0 += p00 + p01; l1 += p10 + p11;

            uint32_t af[4] = { cvt_tf32(p00), cvt_tf32(p10),
                               cvt_tf32(p01), cvt_tf32(p11) };
            const float* Vr = &Vs[(size_t)g * 512 + lane * 4];
#pragma unroll
            for (int p = 0; p < 4; p++) {
                float4 v = *reinterpret_cast<const float4*>(Vr + p * 128);
                uint32_t bfa[2] = { __float_as_uint(v.x), __float_as_uint(v.y) };
                uint32_t bfb[2] = { __float_as_uint(v.z), __float_as_uint(v.w) };
                mma_tf32(od[p],     af, bfa);
                mma_tf32(od[p + 4], af, bfb);
            }
        }
    }

    // ---- normalize and write O (tf32, sigma16-permuted DIMC) ----
    l0 += __shfl_xor_sync(0xffffffffu, l0, 1);
    l0 += __shfl_xor_sync(0xffffffffu, l0, 2);
    l1 += __shfl_xor_sync(0xffffffffu, l1, 1);
    l1 += __shfl_xor_sync(0xffffffffu, l1, 2);
    float inv0 = 1.f / l0, inv1 = 1.f / l1;

    size_t orow0 = (size_t)b * SEQ + q0 + wid * 16 + r;
#pragma unroll
    for (int nf = 0; nf < 8; nf++) {
        int d0 = nf * 8 + 2 * q;
        int s0 = h * HDIM + sig16(d0);
        int s1 = h * HDIM + sig16(d0 + 1);
        g_O[orow0 * DIMC + s0]       = tf32f(od[nf][0] * inv0);
        g_O[orow0 * DIMC + s1]       = tf32f(od[nf][1] * inv0);
        g_O[(orow0 + 8) * DIMC + s0] = tf32f(od[nf][2] * inv1);
        g_O[(orow0 + 8) * DIMC + s1] = tf32f(od[nf][3] * inv1);
    }
}

// ============================================================================
// Kernel 3: out = O @ Wproj^T + bias (unchanged)
// ============================================================================
__global__ __launch_bounds__(256) void proj_tc(const float* __restrict__ bias,
                                               float* __restrict__ out) {
    extern __shared__ float smf[];
    float acc[4][4][4];
    int brow = blockIdx.y * 128, bcol = blockIdx.x * 128;
    gemm_core<128, 24, 4, 4, 2>(g_O + (size_t)brow * DIMC, DIMC,
                                g_Wp + (size_t)bcol * DIMC, DIMC, acc, smf);
    int lane = threadIdx.x & 31, wid = threadIdx.x >> 5;
    int wm = wid % 2, wn = wid / 2, r = lane >> 2, q = lane & 3;

#pragma unroll
    for (int mf = 0; mf < 4; mf++)
#pragma unroll
        for (int nf = 0; nf < 4; nf++) {
            int col = bcol + wn * 32 + nf * 8 + q * 2;
            float2 bb = *reinterpret_cast<const float2*>(&bias[col]);
#pragma unroll
            for (int rr = 0; rr < 2; rr++) {
                int row = brow + wm * 64 + mf * 16 + r + rr * 8;
                float v0 = acc[mf][nf][rr * 2 + 0] + bb.x;
                float v1 = acc[mf][nf][rr * 2 + 1] + bb.y;
                *reinterpret_cast<float2*>(&out[(size_t)row * DIMC + col]) = make_float2(v0, v1);
            }
        }
}

// ============================================================================
extern "C" void kernel_launch(void* const* d_in, const int* in_sizes, int n_in,
                              void* d_out, int out_size) {
    (void)in_sizes; (void)n_in; (void)out_size;
    const float* x        = (const float*)d_in[0];
    const float* w_qkv    = (const float*)d_in[1];
    const float* w_proj   = (const float*)d_in[2];
    const float* b_proj   = (const float*)d_in[3];
    const float* att_mask = (const float*)d_in[4];
    float* out = (float*)d_out;

    const int GEMM_SMEM  = (4 * 128 * LDK) * (int)sizeof(float);    // 98304
    const int FLASH_SMEM = (3 * STAGE_F) * (int)sizeof(float);      // 110592

    cudaFuncSetAttribute(qkv_tc,   cudaFuncAttributeMaxDynamicSharedMemorySize, GEMM_SMEM);
    cudaFuncSetAttribute(proj_tc,  cudaFuncAttributeMaxDynamicSharedMemorySize, GEMM_SMEM);
    cudaFuncSetAttribute(flash_tc, cudaFuncAttributeMaxDynamicSharedMemorySize, FLASH_SMEM);

    round_all<<<NB_X + NB_WQ + NB_WP, 256>>>(x, w_qkv, w_proj);
    presig   <<<(NHEADS * SEQ * SEQ) / 1024, 256>>>(att_mask);

    qkv_tc  <<<dim3(2304 / 128, MROWS / 128), 256, GEMM_SMEM>>>();
    flash_tc<<<dim3(PAIRS, SEQ / 128), 256, FLASH_SMEM>>>();
    proj_tc <<<dim3(DIMC / 128, MROWS / 128), 256, GEMM_SMEM>>>(b_proj, out);
}

// round 14
// speedup vs baseline: 1.1607x; 1.1607x over previous
#include <cuda_runtime.h>
#include <cuda_fp16.h>
#include <cstdint>
#include <math.h>

#define DIMC   768
#define NHEADS 12
#define HDIM   64
#define BATCH  8
#define SEQ    1024
#define MROWS  (BATCH*SEQ)
#define PAIRS  (BATCH*NHEADS)
#define ATT_SCALE 0.125f

// ---------------- scratch (static device memory; no cudaMalloc allowed) ----
// g_Qh/g_Kh: fp16, d-dim sigma32-permuted (fp16 m16n8k16 fragment order)
// g_Vh     : fp16, FRAGMENT-MAJOR for PV: [pair][gp(64)][nfp(4)][lane(32)][8]
//            8 halves = { b0(nf),b1(nf), b0(nf+4),b1(nf+4) } as half2 pairs
// g_O      : fp32 tf32-rounded, DIMC sigma16-permuted (for tf32 proj GEMM)
__device__ __align__(16) __half g_Qh [(size_t)PAIRS*SEQ*HDIM];
__device__ __align__(16) __half g_Kh [(size_t)PAIRS*SEQ*HDIM];
__device__ __align__(16) __half g_Vh [(size_t)PAIRS*SEQ*HDIM];
__device__ __align__(16) float  g_O   [(size_t)MROWS*DIMC];
__device__ __align__(16) float  g_Msig[(size_t)NHEADS*SEQ*SEQ];
__device__ __align__(16) float  g_Xr  [(size_t)MROWS*DIMC];
__device__ __align__(16) float  g_Wq  [(size_t)3*DIMC*DIMC];
__device__ __align__(16) float  g_Wp  [(size_t)DIMC*DIMC];

// ======================= helpers ===========================================
__device__ __forceinline__ uint32_t cvt_tf32(float x) {
    uint32_t r; asm("cvt.rna.tf32.f32 %0, %1;" : "=r"(r) : "f"(x)); return r;
}
__device__ __forceinline__ float tf32f(float x) {
    return __uint_as_float(cvt_tf32(x));
}
__device__ __forceinline__ int sig16(int j) {          // tf32 GEMM k-perm
    int jj = j & 15, jjj = jj & 7;
    return (j & ~15) + (jjj & 3) * 4 + (jj >> 3) * 2 + (jjj >> 2);
}
__device__ __forceinline__ int sig32h(int k) {         // fp16 frag k-perm (k<32)
    return ((k & 7) >> 1) * 8 + ((k >> 4) & 1) * 4 + (k & 1) + ((k >> 3) & 1) * 2;
}
__device__ __forceinline__ void mma_tf32(float (&c)[4], const uint32_t (&a)[4],
                                         const uint32_t (&b)[2]) {
    asm volatile("mma.sync.aligned.m16n8k8.row.col.f32.tf32.tf32.f32 "
                 "{%0,%1,%2,%3}, {%4,%5,%6,%7}, {%8,%9}, {%0,%1,%2,%3};"
                 : "+f"(c[0]), "+f"(c[1]), "+f"(c[2]), "+f"(c[3])
                 : "r"(a[0]), "r"(a[1]), "r"(a[2]), "r"(a[3]),
                   "r"(b[0]), "r"(b[1]));
}
__device__ __forceinline__ void mma_f16(float (&c)[4], const uint32_t (&a)[4],
                                        uint32_t b0, uint32_t b1) {
    asm volatile("mma.sync.aligned.m16n8k16.row.col.f32.f16.f16.f32 "
                 "{%0,%1,%2,%3}, {%4,%5,%6,%7}, {%8,%9}, {%0,%1,%2,%3};"
                 : "+f"(c[0]), "+f"(c[1]), "+f"(c[2]), "+f"(c[3])
                 : "r"(a[0]), "r"(a[1]), "r"(a[2]), "r"(a[3]),
                   "r"(b0), "r"(b1));
}
__device__ __forceinline__ uint32_t h2u(__half2 h) {
    uint32_t u; *reinterpret_cast<__half2*>(&u) = h; return u;
}
__device__ __forceinline__ uint32_t smem_u32(const void* p) {
    uint32_t a;
    asm("{ .reg .u64 t; cvta.to.shared.u64 t, %1; cvt.u32.u64 %0, t; }"
        : "=r"(a) : "l"(p));
    return a;
}
#define CP_ASYNC16(dst, src) \
    asm volatile("cp.async.cg.shared.global [%0], [%1], 16;" \
                 :: "r"(dst), "l"(src) : "memory")
#define CP_COMMIT() asm volatile("cp.async.commit_group;" ::: "memory")
#define CP_WAIT(n)  asm volatile("cp.async.wait_group %0;" :: "n"(n) : "memory")

// ============================================================================
// Pre-kernels: fused tf32 round + sigma16 permutation; presig
// ============================================================================
#define NB_X  (MROWS * DIMC / 1024)
#define NB_WQ (3 * DIMC * DIMC / 1024)
#define NB_WP (DIMC * DIMC / 1024)

__device__ __forceinline__ void round_perm_elem(const float* __restrict__ src,
                                                float* __restrict__ dst,
                                                size_t i) {
    float4 v = *reinterpret_cast<const float4*>(src + i);
    int col = (int)(i % DIMC);
    size_t rowbase = i - col;
    int off = ((col >> 3) & 1) * 2 + ((col >> 2) & 1);
    size_t d0 = rowbase + (col & ~15) + off;
    dst[d0]      = tf32f(v.x);
    dst[d0 + 4]  = tf32f(v.y);
    dst[d0 + 8]  = tf32f(v.z);
    dst[d0 + 12] = tf32f(v.w);
}

__global__ __launch_bounds__(256) void round_all(const float* __restrict__ x,
                                                 const float* __restrict__ wq,
                                                 const float* __restrict__ wp) {
    int blk = blockIdx.x;
    if (blk < NB_X) {
        round_perm_elem(x, g_Xr, ((size_t)blk * 256 + threadIdx.x) * 4);
    } else if (blk < NB_X + NB_WQ) {
        round_perm_elem(wq, g_Wq, ((size_t)(blk - NB_X) * 256 + threadIdx.x) * 4);
    } else {
        round_perm_elem(wp, g_Wp, ((size_t)(blk - NB_X - NB_WQ) * 256 + threadIdx.x) * 4);
    }
}

__global__ __launch_bounds__(256) void presig(const float* __restrict__ m) {
    size_t i = ((size_t)blockIdx.x * 256 + threadIdx.x) * 4;
    float4 v = *reinterpret_cast<const float4*>(m + i);
    float4 o;
    o.x = ATT_SCALE / (1.f + __expf(-v.x));
    o.y = ATT_SCALE / (1.f + __expf(-v.y));
    o.z = ATT_SCALE / (1.f + __expf(-v.z));
    o.w = ATT_SCALE / (1.f + __expf(-v.w));
    *reinterpret_cast<float4*>(g_Msig + i) = o;
}

// ============================================================================
// NT GEMM core (tf32, unchanged from R12): cp.async 2-stage, LDK=48, LDS.128
// ============================================================================
#define LDK 48

template <int BN, int NC, int MF, int NF, int WMDIV>
__device__ __forceinline__ void gemm_core(const float* __restrict__ A, int lda,
                                          const float* __restrict__ B, int ldb,
                                          float (&acc)[MF][NF][4],
                                          float* smem) {
    float* As[2] = { smem, smem + 128 * LDK };
    float* Bs[2] = { smem + 2 * 128 * LDK, smem + 2 * 128 * LDK + BN * LDK };

    const int tid  = threadIdx.x;
    const int lane = tid & 31;
    const int wid  = tid >> 5;
    const int wm   = wid % WMDIV;
    const int wn   = wid / WMDIV;
    const int mrow0 = wm * (MF * 16);
    const int ncol0 = wn * (NF * 8);
    const int r = lane >> 2, q = lane & 3;

#pragma unroll
    for (int mf = 0; mf < MF; mf++)
#pragma unroll
        for (int nf = 0; nf < NF; nf++)
#pragma unroll
            for (int i = 0; i < 4; i++) acc[mf][nf][i] = 0.f;

    const int arow = tid >> 3, ac = (tid & 7) * 4;

    auto copy = [&](int i, int buf) {
        int k0 = i * 32;
#pragma unroll
        for (int p = 0; p < 4; p++) {
            int row = arow + p * 32;
            CP_ASYNC16(smem_u32(&As[buf][row * LDK + ac]),
                       A + (size_t)row * lda + k0 + ac);
        }
#pragma unroll
        for (int p = 0; p < BN / 32; p++) {
            int row = arow + p * 32;
            CP_ASYNC16(smem_u32(&Bs[buf][row * LDK + ac]),
                       B + (size_t)row * ldb + k0 + ac);
        }
    };

    copy(0, 0); CP_COMMIT();
    copy(1, 1); CP_COMMIT();
    CP_WAIT(1);
    __syncthreads();

#pragma unroll 1
    for (int i = 0; i < NC; i++) {
        const int buf = i & 1;
        const float* Ab = As[buf];
        const float* Bb = Bs[buf];
#pragma unroll
        for (int blk = 0; blk < 2; blk++) {
            uint32_t af[MF][2][4], bf[NF][2][2];
#pragma unroll
            for (int mf = 0; mf < MF; mf++) {
                const float* ap = &Ab[(mrow0 + mf * 16 + r) * LDK + blk * 16 + 4 * q];
                float4 a0 = *reinterpret_cast<const float4*>(ap);
                float4 a1 = *reinterpret_cast<const float4*>(ap + 8 * LDK);
                af[mf][0][0] = __float_as_uint(a0.x); af[mf][0][1] = __float_as_uint(a1.x);
                af[mf][0][2] = __float_as_uint(a0.y); af[mf][0][3] = __float_as_uint(a1.y);
                af[mf][1][0] = __float_as_uint(a0.z); af[mf][1][1] = __float_as_uint(a1.z);
                af[mf][1][2] = __float_as_uint(a0.w); af[mf][1][3] = __float_as_uint(a1.w);
            }
#pragma unroll
            for (int nf = 0; nf < NF; nf++) {
                float4 b = *reinterpret_cast<const float4*>(
                    &Bb[(ncol0 + nf * 8 + r) * LDK + blk * 16 + 4 * q]);
                bf[nf][0][0] = __float_as_uint(b.x); bf[nf][0][1] = __float_as_uint(b.y);
                bf[nf][1][0] = __float_as_uint(b.z); bf[nf][1][1] = __float_as_uint(b.w);
            }
#pragma unroll
            for (int mf = 0; mf < MF; mf++)
#pragma unroll
                for (int nf = 0; nf < NF; nf++) {
                    mma_tf32(acc[mf][nf], af[mf][0], bf[nf][0]);
                    mma_tf32(acc[mf][nf], af[mf][1], bf[nf][1]);
                }
        }
        if (i == NC - 1) break;
        __syncthreads();
        if (i + 2 < NC) { copy(i + 2, buf); CP_COMMIT(); CP_WAIT(1); }
        else            { CP_WAIT(0); }
        __syncthreads();
    }
}

// ============================================================================
// Kernel 1: QKV projection + scatter. Q/K: fp16 sigma32h. V: fp16 frag-major.
// ============================================================================
__global__ __launch_bounds__(256) void qkv_tc() {
    extern __shared__ float smf[];
    float acc[4][4][4];
    int brow = blockIdx.y * 128, bcol = blockIdx.x * 128;
    gemm_core<128, 24, 4, 4, 2>(g_Xr + (size_t)brow * DIMC, DIMC,
                                g_Wq + (size_t)bcol * DIMC, DIMC, acc, smf);
    int lane = threadIdx.x & 31, wid = threadIdx.x >> 5;
    int wm = wid % 2, wn = wid / 2, r = lane >> 2, q = lane & 3;
    int part = bcol / 768, rem0 = bcol - part * 768;

#pragma unroll
    for (int mf = 0; mf < 4; mf++)
#pragma unroll
        for (int nf = 0; nf < 4; nf++) {
            int col = rem0 + wn * 32 + nf * 8 + 2 * q;
            int h = col >> 6, d = col & 63;        // d even
#pragma unroll
            for (int rr = 0; rr < 2; rr++) {
                int m = brow + wm * 64 + mf * 16 + r + rr * 8;
                int b = m >> 10, nq = m & 1023;
                float v0 = acc[mf][nf][rr * 2 + 0];
                float v1 = acc[mf][nf][rr * 2 + 1];
                int pairIdx = b * NHEADS + h;
                if (part < 2) {
                    __half* dst = (part == 0) ? g_Qh : g_Kh;
                    int blk = d & ~31, kk = d & 31;
                    int pos = sig32h(kk);          // even
                    size_t base = ((size_t)pairIdx * SEQ + nq) * HDIM + blk + pos;
                    *reinterpret_cast<__half2*>(dst + base) = __floats2half2_rn(v0, v1);
                } else {
                    // fragment-major V
                    int g = nq >> 3, gp = g >> 1, hi = g & 1;
                    int qt = (nq & 7) >> 1, e = nq & 1;
                    int nfv = d >> 3, rl = d & 7;
                    size_t off = ((size_t)pairIdx * SEQ) * HDIM
                               + (size_t)gp * 1024
                               + (size_t)(nfv & 3) * 256
                               + (size_t)(rl * 4 + qt) * 8
                               + (nfv >> 2) * 4 + hi * 2 + e;
                    g_Vh[off]      = __float2half_rn(v0);
                    g_Vh[off + 32] = __float2half_rn(v1);   // channel d+1 -> lane+4
                }
            }
        }
}

// ============================================================================
// Kernel 2: FUSED flash attention, fp16 m16n8k16.
//  - 64 MMAs/iter (half of tf32), smem 20.5KB/stage fp16, 3-stage ring
//  - Q frags (16 regs) from sigma32h global via LDG.128
//  - K: stride 96 halves -> conflict-free LDS.128 (2 k-steps per load)
//  - V: fragment-major, one LDS.128 feeds od[nfp] and od[nfp+4]
//  - P packed to fp16 in registers (S c-frag == PV a-frag across group pairs)
// ============================================================================
#define KT 64
#define LDHK 96
#define K_STAGE_H (64 * LDHK)          // 6144 halves
#define V_STAGE_H 4096
#define STAGE_H (K_STAGE_H + V_STAGE_H) // 10240 halves = 20480 B
#define NITER (SEQ / KT)

__global__ __launch_bounds__(256, 2) void flash_tc() {
    extern __shared__ __half smh[];

    const int tid = threadIdx.x, lane = tid & 31, wid = tid >> 5;
    const int r = lane >> 2, q = lane & 3;
    const int pair = blockIdx.x;
    const int h = pair % NHEADS, b = pair / NHEADS;
    const int q0 = blockIdx.y * 128;

    const __half* Qg = g_Qh + (size_t)pair * SEQ * HDIM;
    const __half* Kg = g_Kh + (size_t)pair * SEQ * HDIM;
    const __half* Vg = g_Vh + (size_t)pair * SEQ * HDIM;
    const float*  Mg = g_Msig + (size_t)h * SEQ * SEQ;

    auto copyKV = [&](int kb, int buf) {
        __half* Kd = smh + buf * STAGE_H;
        __half* Vd = Kd + K_STAGE_H;
        const __half* Ksrc = Kg + (size_t)(kb * KT) * HDIM;
        const __half* Vsrc = Vg + (size_t)kb * V_STAGE_H;
#pragma unroll
        for (int p = 0; p < 2; p++) {
            int idx = tid + p * 256;
            int row = idx >> 3, c = idx & 7;
            CP_ASYNC16(smem_u32(Kd + row * LDHK + c * 8), Ksrc + row * HDIM + c * 8);
            CP_ASYNC16(smem_u32(Vd + idx * 8), Vsrc + (size_t)idx * 8);
        }
    };

    copyKV(0, 0); CP_COMMIT();
    copyKV(1, 1); CP_COMMIT();

    // ---- Q fragments (fp16, 16 regs) via LDG.128 ----
    uint32_t qa[4][4];                 // [k-step][a-reg]
    {
        const __half* qr0 = Qg + (size_t)(q0 + wid * 16 + r) * HDIM;
        const __half* qr1 = qr0 + 8 * HDIM;
#pragma unroll
        for (int blk = 0; blk < 2; blk++) {
            uint4 u0 = *reinterpret_cast<const uint4*>(qr0 + blk * 32 + q * 8);
            uint4 u1 = *reinterpret_cast<const uint4*>(qr1 + blk * 32 + q * 8);
            qa[2 * blk][0]     = u0.x; qa[2 * blk][2]     = u0.y;
            qa[2 * blk][1]     = u1.x; qa[2 * blk][3]     = u1.y;
            qa[2 * blk + 1][0] = u0.z; qa[2 * blk + 1][2] = u0.w;
            qa[2 * blk + 1][1] = u1.z; qa[2 * blk + 1][3] = u1.w;
        }
    }

    float od[8][4];
#pragma unroll
    for (int nf = 0; nf < 8; nf++)
#pragma unroll
        for (int i = 0; i < 4; i++) od[nf][i] = 0.f;
    float l0 = 0.f, l1 = 0.f;

    const int row_s0 = q0 + wid * 16 + r;
    const float* Mrow0 = Mg + (size_t)row_s0 * SEQ + 2 * q;
    const float* Mrow1 = Mrow0 + 8 * SEQ;

#pragma unroll 1
    for (int kb = 0; kb < NITER; kb++) {
        if (kb == NITER - 1) { CP_WAIT(0); } else { CP_WAIT(1); }
        __syncthreads();                 // stage kb visible; compute kb-1 done
        if (kb + 2 < NITER) {
            copyKV(kb + 2, (kb + 2) % 3);
            CP_COMMIT();
        }

        const __half* Ks = smh + (kb % 3) * STAGE_H;
        const __half* Vs = Ks + K_STAGE_H;

        // ---- stream group-PAIRS: S (fp16 k16) -> gate/exp -> pack -> PV ----
#pragma unroll
        for (int gp = 0; gp < 4; gp++) {
            float s0a[4] = {0.f, 0.f, 0.f, 0.f};
            float s1a[4] = {0.f, 0.f, 0.f, 0.f};
            const __half* Kr0 = Ks + ((2 * gp)     * 8 + r) * LDHK;
            const __half* Kr1 = Ks + ((2 * gp + 1) * 8 + r) * LDHK;
            uint4 k00 = *reinterpret_cast<const uint4*>(Kr0 + q * 8);
            uint4 k01 = *reinterpret_cast<const uint4*>(Kr0 + 32 + q * 8);
            uint4 k10 = *reinterpret_cast<const uint4*>(Kr1 + q * 8);
            uint4 k11 = *reinterpret_cast<const uint4*>(Kr1 + 32 + q * 8);
            mma_f16(s0a, qa[0], k00.x, k00.y);
            mma_f16(s1a, qa[0], k10.x, k10.y);
            mma_f16(s0a, qa[1], k00.z, k00.w);
            mma_f16(s1a, qa[1], k10.z, k10.w);
            mma_f16(s0a, qa[2], k01.x, k01.y);
            mma_f16(s1a, qa[2], k11.x, k11.y);
            mma_f16(s0a, qa[3], k01.z, k01.w);
            mma_f16(s1a, qa[3], k11.z, k11.w);

            int col0 = kb * KT + gp * 16;
            float2 m00 = *reinterpret_cast<const float2*>(Mrow0 + col0);
            float2 m01 = *reinterpret_cast<const float2*>(Mrow0 + col0 + 8);
            float2 m10 = *reinterpret_cast<const float2*>(Mrow1 + col0);
            float2 m11 = *reinterpret_cast<const float2*>(Mrow1 + col0 + 8);

            float p0c0 = __expf(s0a[0] * m00.x);
            float p0c1 = __expf(s0a[1] * m00.y);
            float p0c2 = __expf(s0a[2] * m10.x);
            float p0c3 = __expf(s0a[3] * m10.y);
            float p1c0 = __expf(s1a[0] * m01.x);
            float p1c1 = __expf(s1a[1] * m01.y);
            float p1c2 = __expf(s1a[2] * m11.x);
            float p1c3 = __expf(s1a[3] * m11.y);
            l0 += p0c0 + p0c1 + p1c0 + p1c1;
            l1 += p0c2 + p0c3 + p1c2 + p1c3;

            uint32_t af[4];
            af[0] = h2u(__floats2half2_rn(p0c0, p0c1));   // row r,   keys g0
            af[1] = h2u(__floats2half2_rn(p0c2, p0c3));   // row r+8, keys g0
            af[2] = h2u(__floats2half2_rn(p1c0, p1c1));   // row r,   keys g1
            af[3] = h2u(__floats2half2_rn(p1c2, p1c3));   // row r+8, keys g1

            const __half* Vr = Vs + gp * 1024 + lane * 8;
#pragma unroll
            for (int nfp = 0; nfp < 4; nfp++) {
                uint4 v = *reinterpret_cast<const uint4*>(Vr + nfp * 256);
                mma_f16(od[nfp],     af, v.x, v.y);
                mma_f16(od[nfp + 4], af, v.z, v.w);
            }
        }
    }

    // ---- normalize and write O (tf32, sigma16-permuted DIMC for proj) ----
    l0 += __shfl_xor_sync(0xffffffffu, l0, 1);
    l0 += __shfl_xor_sync(0xffffffffu, l0, 2);
    l1 += __shfl_xor_sync(0xffffffffu, l1, 1);
    l1 += __shfl_xor_sync(0xffffffffu, l1, 2);
    float inv0 = 1.f / l0, inv1 = 1.f / l1;

    size_t orow0 = (size_t)b * SEQ + q0 + wid * 16 + r;
#pragma unroll
    for (int nf = 0; nf < 8; nf++) {
        int d0 = nf * 8 + 2 * q;
        int s0 = h * HDIM + sig16(d0);
        int s1 = h * HDIM + sig16(d0 + 1);
        g_O[orow0 * DIMC + s0]       = tf32f(od[nf][0] * inv0);
        g_O[orow0 * DIMC + s1]       = tf32f(od[nf][1] * inv0);
        g_O[(orow0 + 8) * DIMC + s0] = tf32f(od[nf][2] * inv1);
        g_O[(orow0 + 8) * DIMC + s1] = tf32f(od[nf][3] * inv1);
    }
}

// ============================================================================
// Kernel 3: out = O @ Wproj^T + bias (tf32 core, unchanged)
// ============================================================================
__global__ __launch_bounds__(256) void proj_tc(const float* __restrict__ bias,
                                               float* __restrict__ out) {
    extern __shared__ float smf[];
    float acc[4][4][4];
    int brow = blockIdx.y * 128, bcol = blockIdx.x * 128;
    gemm_core<128, 24, 4, 4, 2>(g_O + (size_t)brow * DIMC, DIMC,
                                g_Wp + (size_t)bcol * DIMC, DIMC, acc, smf);
    int lane = threadIdx.x & 31, wid = threadIdx.x >> 5;
    int wm = wid % 2, wn = wid / 2, r = lane >> 2, q = lane & 3;

#pragma unroll
    for (int mf = 0; mf < 4; mf++)
#pragma unroll
        for (int nf = 0; nf < 4; nf++) {
            int col = bcol + wn * 32 + nf * 8 + q * 2;
            float2 bb = *reinterpret_cast<const float2*>(&bias[col]);
#pragma unroll
            for (int rr = 0; rr < 2; rr++) {
                int row = brow + wm * 64 + mf * 16 + r + rr * 8;
                float v0 = acc[mf][nf][rr * 2 + 0] + bb.x;
                float v1 = acc[mf][nf][rr * 2 + 1] + bb.y;
                *reinterpret_cast<float2*>(&out[(size_t)row * DIMC + col]) = make_float2(v0, v1);
            }
        }
}

// ============================================================================
extern "C" void kernel_launch(void* const* d_in, const int* in_sizes, int n_in,
                              void* d_out, int out_size) {
    (void)in_sizes; (void)n_in; (void)out_size;
    const float* x        = (const float*)d_in[0];
    const float* w_qkv    = (const float*)d_in[1];
    const float* w_proj   = (const float*)d_in[2];
    const float* b_proj   = (const float*)d_in[3];
    const float* att_mask = (const float*)d_in[4];
    float* out = (float*)d_out;

    const int GEMM_SMEM  = (4 * 128 * LDK) * (int)sizeof(float);       // 98304
    const int FLASH_SMEM = 3 * STAGE_H * (int)sizeof(__half);          // 61440

    cudaFuncSetAttribute(qkv_tc,   cudaFuncAttributeMaxDynamicSharedMemorySize, GEMM_SMEM);
    cudaFuncSetAttribute(proj_tc,  cudaFuncAttributeMaxDynamicSharedMemorySize, GEMM_SMEM);
    cudaFuncSetAttribute(flash_tc, cudaFuncAttributeMaxDynamicSharedMemorySize, FLASH_SMEM);

    round_all<<<NB_X + NB_WQ + NB_WP, 256>>>(x, w_qkv, w_proj);
    presig   <<<(NHEADS * SEQ * SEQ) / 1024, 256>>>(att_mask);

    qkv_tc  <<<dim3(2304 / 128, MROWS / 128), 256, GEMM_SMEM>>>();
    flash_tc<<<dim3(PAIRS, SEQ / 128), 256, FLASH_SMEM>>>();
    proj_tc <<<dim3(DIMC / 128, MROWS / 128), 256, GEMM_SMEM>>>(b_proj, out);
}

// round 15
// speedup vs baseline: 1.7935x; 1.5452x over previous
#include <cuda_runtime.h>
#include <cuda_fp16.h>
#include <cstdint>
#include <math.h>

#define DIMC   768
#define NHEADS 12
#define HDIM   64
#define BATCH  8
#define SEQ    1024
#define MROWS  (BATCH*SEQ)
#define PAIRS  (BATCH*NHEADS)
#define ATT_SCALE 0.125f

// ---------------- scratch (static device memory; no cudaMalloc allowed) ----
// All MMA operands fp16, sigma32h-permuted along the contraction dim.
// g_Vh: fragment-major fp16 V (see R14).  g_Oh: fp16 attn output for proj.
__device__ __align__(16) __half g_Qh [(size_t)PAIRS*SEQ*HDIM];
__device__ __align__(16) __half g_Kh [(size_t)PAIRS*SEQ*HDIM];
__device__ __align__(16) __half g_Vh [(size_t)PAIRS*SEQ*HDIM];
__device__ __align__(16) __half g_Oh [(size_t)MROWS*DIMC];
__device__ __align__(16) __half g_Xh [(size_t)MROWS*DIMC];
__device__ __align__(16) __half g_Wqh[(size_t)3*DIMC*DIMC];
__device__ __align__(16) __half g_Wph[(size_t)DIMC*DIMC];
__device__ __align__(16) float  g_Msig[(size_t)NHEADS*SEQ*SEQ];

// ======================= helpers ===========================================
__device__ __forceinline__ int sig32h(int k) {         // fp16 frag k-perm (k<32)
    return ((k & 7) >> 1) * 8 + ((k >> 4) & 1) * 4 + (k & 1) + ((k >> 3) & 1) * 2;
}
__device__ __forceinline__ void mma_f16(float (&c)[4], const uint32_t (&a)[4],
                                        uint32_t b0, uint32_t b1) {
    asm volatile("mma.sync.aligned.m16n8k16.row.col.f32.f16.f16.f32 "
                 "{%0,%1,%2,%3}, {%4,%5,%6,%7}, {%8,%9}, {%0,%1,%2,%3};"
                 : "+f"(c[0]), "+f"(c[1]), "+f"(c[2]), "+f"(c[3])
                 : "r"(a[0]), "r"(a[1]), "r"(a[2]), "r"(a[3]),
                   "r"(b0), "r"(b1));
}
__device__ __forceinline__ uint32_t h2u(__half2 h) {
    uint32_t u; *reinterpret_cast<__half2*>(&u) = h; return u;
}
__device__ __forceinline__ uint32_t smem_u32(const void* p) {
    uint32_t a;
    asm("{ .reg .u64 t; cvta.to.shared.u64 t, %1; cvt.u32.u64 %0, t; }"
        : "=r"(a) : "l"(p));
    return a;
}
#define CP_ASYNC16(dst, src) \
    asm volatile("cp.async.cg.shared.global [%0], [%1], 16;" \
                 :: "r"(dst), "l"(src) : "memory")
#define CP_COMMIT() asm volatile("cp.async.commit_group;" ::: "memory")
#define CP_WAIT(n)  asm volatile("cp.async.wait_group %0;" :: "n"(n) : "memory")

// ============================================================================
// Pre-kernels: fp16 round + sigma32h permutation of x / w_qkv / w_proj; presig
// ============================================================================
#define NB_X  (MROWS * DIMC / 1024)
#define NB_WQ (3 * DIMC * DIMC / 1024)
#define NB_WP (DIMC * DIMC / 1024)

__device__ __forceinline__ void round_perm_h(const float* __restrict__ src,
                                             __half* __restrict__ dst,
                                             size_t i) {
    float4 v = *reinterpret_cast<const float4*>(src + i);
    int col = (int)(i % DIMC);                 // multiple of 4
    size_t rowbase = i - col;
    int blk = col & ~31;
    int p0 = sig32h(col & 31);                 // col even -> p0 even; p(col+2)=p0+8
    __half* base = dst + rowbase + blk;
    *reinterpret_cast<__half2*>(base + p0)     = __floats2half2_rn(v.x, v.y);
    *reinterpret_cast<__half2*>(base + p0 + 8) = __floats2half2_rn(v.z, v.w);
}

__global__ __launch_bounds__(256) void round_all(const float* __restrict__ x,
                                                 const float* __restrict__ wq,
                                                 const float* __restrict__ wp) {
    int blk = blockIdx.x;
    if (blk < NB_X) {
        round_perm_h(x, g_Xh, ((size_t)blk * 256 + threadIdx.x) * 4);
    } else if (blk < NB_X + NB_WQ) {
        round_perm_h(wq, g_Wqh, ((size_t)(blk - NB_X) * 256 + threadIdx.x) * 4);
    } else {
        round_perm_h(wp, g_Wph, ((size_t)(blk - NB_X - NB_WQ) * 256 + threadIdx.x) * 4);
    }
}

__global__ __launch_bounds__(256) void presig(const float* __restrict__ m) {
    size_t i = ((size_t)blockIdx.x * 256 + threadIdx.x) * 4;
    float4 v = *reinterpret_cast<const float4*>(m + i);
    float4 o;
    o.x = ATT_SCALE / (1.f + __expf(-v.x));
    o.y = ATT_SCALE / (1.f + __expf(-v.y));
    o.z = ATT_SCALE / (1.f + __expf(-v.z));
    o.w = ATT_SCALE / (1.f + __expf(-v.w));
    *reinterpret_cast<float4*>(g_Msig + i) = o;
}

// ============================================================================
// fp16 NT GEMM core: C[128 x BN] = A[128 x K] * B[BN x K]^T, m16n8k16,
// fp32 accum. k-chunks of 64 halves, cp.async 2-stage, uint4 frag loads.
// Operands sigma32h-permuted along k (same mapping flash validated).
// ============================================================================
#define LDH 96      // halves per 64-half row chunk (192 B)

template <int BN, int NC, int MF, int NF, int WMDIV>
__device__ __forceinline__ void gemm_core_h(const __half* __restrict__ A, int lda,
                                            const __half* __restrict__ B, int ldb,
                                            float (&acc)[MF][NF][4],
                                            __half* smem) {
    __half* As[2] = { smem, smem + 128 * LDH };
    __half* Bs[2] = { smem + 2 * 128 * LDH, smem + 2 * 128 * LDH + BN * LDH };

    const int tid  = threadIdx.x;
    const int lane = tid & 31;
    const int wid  = tid >> 5;
    const int wm   = wid % WMDIV;
    const int wn   = wid / WMDIV;
    const int mrow0 = wm * (MF * 16);
    const int ncol0 = wn * (NF * 8);
    const int r = lane >> 2, q = lane & 3;

#pragma unroll
    for (int mf = 0; mf < MF; mf++)
#pragma unroll
        for (int nf = 0; nf < NF; nf++)
#pragma unroll
            for (int i = 0; i < 4; i++) acc[mf][nf][i] = 0.f;

    const int arow = tid >> 3, ac = (tid & 7) * 8;

    auto copy = [&](int i, int buf) {
        int k0 = i * 64;
#pragma unroll
        for (int p = 0; p < 4; p++) {
            int row = arow + p * 32;
            CP_ASYNC16(smem_u32(&As[buf][row * LDH + ac]),
                       A + (size_t)row * lda + k0 + ac);
        }
#pragma unroll
        for (int p = 0; p < BN / 32; p++) {
            int row = arow + p * 32;
            CP_ASYNC16(smem_u32(&Bs[buf][row * LDH + ac]),
                       B + (size_t)row * ldb + k0 + ac);
        }
    };

    copy(0, 0); CP_COMMIT();
    copy(1, 1); CP_COMMIT();
    CP_WAIT(1);
    __syncthreads();

#pragma unroll 1
    for (int i = 0; i < NC; i++) {
        const int buf = i & 1;
        const __half* Ab = As[buf];
        const __half* Bb = Bs[buf];
#pragma unroll
        for (int blk2 = 0; blk2 < 2; blk2++) {       // 2 x (two k16-steps)
            uint32_t af[MF][2][4];
            uint32_t bf[NF][2][2];
#pragma unroll
            for (int mf = 0; mf < MF; mf++) {
                const __half* ap = &Ab[(mrow0 + mf * 16 + r) * LDH + blk2 * 32 + q * 8];
                uint4 u0 = *reinterpret_cast<const uint4*>(ap);
                uint4 u1 = *reinterpret_cast<const uint4*>(ap + 8 * LDH);
                af[mf][0][0] = u0.x; af[mf][0][2] = u0.y;
                af[mf][0][1] = u1.x; af[mf][0][3] = u1.y;
                af[mf][1][0] = u0.z; af[mf][1][2] = u0.w;
                af[mf][1][1] = u1.z; af[mf][1][3] = u1.w;
            }
#pragma unroll
            for (int nf = 0; nf < NF; nf++) {
                uint4 bv = *reinterpret_cast<const uint4*>(
                    &Bb[(ncol0 + nf * 8 + r) * LDH + blk2 * 32 + q * 8]);
                bf[nf][0][0] = bv.x; bf[nf][0][1] = bv.y;
                bf[nf][1][0] = bv.z; bf[nf][1][1] = bv.w;
            }
#pragma unroll
            for (int mf = 0; mf < MF; mf++)
#pragma unroll
                for (int nf = 0; nf < NF; nf++) {
                    mma_f16(acc[mf][nf], af[mf][0], bf[nf][0][0], bf[nf][0][1]);
                    mma_f16(acc[mf][nf], af[mf][1], bf[nf][1][0], bf[nf][1][1]);
                }
        }
        if (i == NC - 1) break;
        __syncthreads();
        if (i + 2 < NC) { copy(i + 2, buf); CP_COMMIT(); CP_WAIT(1); }
        else            { CP_WAIT(0); }
        __syncthreads();
    }
}

// ============================================================================
// Kernel 1: QKV projection (fp16 core) + scatter to Qh/Kh/Vh (as in R14)
// ============================================================================
__global__ __launch_bounds__(256, 2) void qkv_tc() {
    extern __shared__ __half smh[];
    float acc[4][4][4];
    int brow = blockIdx.y * 128, bcol = blockIdx.x * 128;
    gemm_core_h<128, 12, 4, 4, 2>(g_Xh + (size_t)brow * DIMC, DIMC,
                                  g_Wqh + (size_t)bcol * DIMC, DIMC, acc, smh);
    int lane = threadIdx.x & 31, wid = threadIdx.x >> 5;
    int wm = wid % 2, wn = wid / 2, r = lane >> 2, q = lane & 3;
    int part = bcol / 768, rem0 = bcol - part * 768;

#pragma unroll
    for (int mf = 0; mf < 4; mf++)
#pragma unroll
        for (int nf = 0; nf < 4; nf++) {
            int col = rem0 + wn * 32 + nf * 8 + 2 * q;
            int h = col >> 6, d = col & 63;        // d even
#pragma unroll
            for (int rr = 0; rr < 2; rr++) {
                int m = brow + wm * 64 + mf * 16 + r + rr * 8;
                int b = m >> 10, nq = m & 1023;
                float v0 = acc[mf][nf][rr * 2 + 0];
                float v1 = acc[mf][nf][rr * 2 + 1];
                int pairIdx = b * NHEADS + h;
                if (part < 2) {
                    __half* dst = (part == 0) ? g_Qh : g_Kh;
                    int blk = d & ~31, kk = d & 31;
                    int pos = sig32h(kk);
                    size_t base = ((size_t)pairIdx * SEQ + nq) * HDIM + blk + pos;
                    *reinterpret_cast<__half2*>(dst + base) = __floats2half2_rn(v0, v1);
                } else {
                    int g = nq >> 3, gp = g >> 1, hi = g & 1;
                    int qt = (nq & 7) >> 1, e = nq & 1;
                    int nfv = d >> 3, rl = d & 7;
                    size_t off = ((size_t)pairIdx * SEQ) * HDIM
                               + (size_t)gp * 1024
                               + (size_t)(nfv & 3) * 256
                               + (size_t)(rl * 4 + qt) * 8
                               + (nfv >> 2) * 4 + hi * 2 + e;
                    g_Vh[off]      = __float2half_rn(v0);
                    g_Vh[off + 32] = __float2half_rn(v1);
                }
            }
        }
}

// ============================================================================
// Kernel 2: FUSED flash attention, fp16 m16n8k16 (R14 core; O -> fp16 sig32h)
// ============================================================================
#define KT 64
#define LDHK 96
#define K_STAGE_H (64 * LDHK)
#define V_STAGE_H 4096
#define STAGE_H (K_STAGE_H + V_STAGE_H)
#define NITER (SEQ / KT)

__global__ __launch_bounds__(256, 2) void flash_tc() {
    extern __shared__ __half smh[];

    const int tid = threadIdx.x, lane = tid & 31, wid = tid >> 5;
    const int r = lane >> 2, q = lane & 3;
    const int pair = blockIdx.x;
    const int h = pair % NHEADS, b = pair / NHEADS;
    const int q0 = blockIdx.y * 128;

    const __half* Qg = g_Qh + (size_t)pair * SEQ * HDIM;
    const __half* Kg = g_Kh + (size_t)pair * SEQ * HDIM;
    const __half* Vg = g_Vh + (size_t)pair * SEQ * HDIM;
    const float*  Mg = g_Msig + (size_t)h * SEQ * SEQ;

    auto copyKV = [&](int kb, int buf) {
        __half* Kd = smh + buf * STAGE_H;
        __half* Vd = Kd + K_STAGE_H;
        const __half* Ksrc = Kg + (size_t)(kb * KT) * HDIM;
        const __half* Vsrc = Vg + (size_t)kb * V_STAGE_H;
#pragma unroll
        for (int p = 0; p < 2; p++) {
            int idx = tid + p * 256;
            int row = idx >> 3, c = idx & 7;
            CP_ASYNC16(smem_u32(Kd + row * LDHK + c * 8), Ksrc + row * HDIM + c * 8);
            CP_ASYNC16(smem_u32(Vd + idx * 8), Vsrc + (size_t)idx * 8);
        }
    };

    copyKV(0, 0); CP_COMMIT();
    copyKV(1, 1); CP_COMMIT();

    uint32_t qa[4][4];
    {
        const __half* qr0 = Qg + (size_t)(q0 + wid * 16 + r) * HDIM;
        const __half* qr1 = qr0 + 8 * HDIM;
#pragma unroll
        for (int blk = 0; blk < 2; blk++) {
            uint4 u0 = *reinterpret_cast<const uint4*>(qr0 + blk * 32 + q * 8);
            uint4 u1 = *reinterpret_cast<const uint4*>(qr1 + blk * 32 + q * 8);
            qa[2 * blk][0]     = u0.x; qa[2 * blk][2]     = u0.y;
            qa[2 * blk][1]     = u1.x; qa[2 * blk][3]     = u1.y;
            qa[2 * blk + 1][0] = u0.z; qa[2 * blk + 1][2] = u0.w;
            qa[2 * blk + 1][1] = u1.z; qa[2 * blk + 1][3] = u1.w;
        }
    }

    float od[8][4];
#pragma unroll
    for (int nf = 0; nf < 8; nf++)
#pragma unroll
        for (int i = 0; i < 4; i++) od[nf][i] = 0.f;
    float l0 = 0.f, l1 = 0.f;

    const int row_s0 = q0 + wid * 16 + r;
    const float* Mrow0 = Mg + (size_t)row_s0 * SEQ + 2 * q;
    const float* Mrow1 = Mrow0 + 8 * SEQ;

#pragma unroll 1
    for (int kb = 0; kb < NITER; kb++) {
        if (kb == NITER - 1) { CP_WAIT(0); } else { CP_WAIT(1); }
        __syncthreads();
        if (kb + 2 < NITER) {
            copyKV(kb + 2, (kb + 2) % 3);
            CP_COMMIT();
        }

        const __half* Ks = smh + (kb % 3) * STAGE_H;
        const __half* Vs = Ks + K_STAGE_H;

#pragma unroll
        for (int gp = 0; gp < 4; gp++) {
            float s0a[4] = {0.f, 0.f, 0.f, 0.f};
            float s1a[4] = {0.f, 0.f, 0.f, 0.f};
            const __half* Kr0 = Ks + ((2 * gp)     * 8 + r) * LDHK;
            const __half* Kr1 = Ks + ((2 * gp + 1) * 8 + r) * LDHK;
            uint4 k00 = *reinterpret_cast<const uint4*>(Kr0 + q * 8);
            uint4 k01 = *reinterpret_cast<const uint4*>(Kr0 + 32 + q * 8);
            uint4 k10 = *reinterpret_cast<const uint4*>(Kr1 + q * 8);
            uint4 k11 = *reinterpret_cast<const uint4*>(Kr1 + 32 + q * 8);
            mma_f16(s0a, qa[0], k00.x, k00.y);
            mma_f16(s1a, qa[0], k10.x, k10.y);
            mma_f16(s0a, qa[1], k00.z, k00.w);
            mma_f16(s1a, qa[1], k10.z, k10.w);
            mma_f16(s0a, qa[2], k01.x, k01.y);
            mma_f16(s1a, qa[2], k11.x, k11.y);
            mma_f16(s0a, qa[3], k01.z, k01.w);
            mma_f16(s1a, qa[3], k11.z, k11.w);

            int col0 = kb * KT + gp * 16;
            float2 m00 = *reinterpret_cast<const float2*>(Mrow0 + col0);
            float2 m01 = *reinterpret_cast<const float2*>(Mrow0 + col0 + 8);
            float2 m10 = *reinterpret_cast<const float2*>(Mrow1 + col0);
            float2 m11 = *reinterpret_cast<const float2*>(Mrow1 + col0 + 8);

            float p0c0 = __expf(s0a[0] * m00.x);
            float p0c1 = __expf(s0a[1] * m00.y);
            float p0c2 = __expf(s0a[2] * m10.x);
            float p0c3 = __expf(s0a[3] * m10.y);
            float p1c0 = __expf(s1a[0] * m01.x);
            float p1c1 = __expf(s1a[1] * m01.y);
            float p1c2 = __expf(s1a[2] * m11.x);
            float p1c3 = __expf(s1a[3] * m11.y);
            l0 += p0c0 + p0c1 + p1c0 + p1c1;
            l1 += p0c2 + p0c3 + p1c2 + p1c3;

            uint32_t af[4];
            af[0] = h2u(__floats2half2_rn(p0c0, p0c1));
            af[1] = h2u(__floats2half2_rn(p0c2, p0c3));
            af[2] = h2u(__floats2half2_rn(p1c0, p1c1));
            af[3] = h2u(__floats2half2_rn(p1c2, p1c3));

            const __half* Vr = Vs + gp * 1024 + lane * 8;
#pragma unroll
            for (int nfp = 0; nfp < 4; nfp++) {
                uint4 v = *reinterpret_cast<const uint4*>(Vr + nfp * 256);
                mma_f16(od[nfp],     af, v.x, v.y);
                mma_f16(od[nfp + 4], af, v.z, v.w);
            }
        }
    }

    // ---- normalize and write O (fp16, sigma32h-permuted DIMC for proj) ----
    l0 += __shfl_xor_sync(0xffffffffu, l0, 1);
    l0 += __shfl_xor_sync(0xffffffffu, l0, 2);
    l1 += __shfl_xor_sync(0xffffffffu, l1, 1);
    l1 += __shfl_xor_sync(0xffffffffu, l1, 2);
    float inv0 = 1.f / l0, inv1 = 1.f / l1;

    size_t orow0 = (size_t)b * SEQ + q0 + wid * 16 + r;
#pragma unroll
    for (int nf = 0; nf < 8; nf++) {
        int d0 = nf * 8 + 2 * q;                       // even
        int colblk = h * HDIM + (d0 & ~31);
        int pos = sig32h(d0 & 31);                     // even; d0+1 -> pos+1
        *reinterpret_cast<__half2*>(&g_Oh[orow0 * DIMC + colblk + pos]) =
            __floats2half2_rn(od[nf][0] * inv0, od[nf][1] * inv0);
        *reinterpret_cast<__half2*>(&g_Oh[(orow0 + 8) * DIMC + colblk + pos]) =
            __floats2half2_rn(od[nf][2] * inv1, od[nf][3] * inv1);
    }
}

// ============================================================================
// Kernel 3: out = O @ Wproj^T + bias (fp16 core)
// ============================================================================
__global__ __launch_bounds__(256, 2) void proj_tc(const float* __restrict__ bias,
                                                  float* __restrict__ out) {
    extern __shared__ __half smh[];
    float acc[4][4][4];
    int brow = blockIdx.y * 128, bcol = blockIdx.x * 128;
    gemm_core_h<128, 12, 4, 4, 2>(g_Oh + (size_t)brow * DIMC, DIMC,
                                  g_Wph + (size_t)bcol * DIMC, DIMC, acc, smh);
    int lane = threadIdx.x & 31, wid = threadIdx.x >> 5;
    int wm = wid % 2, wn = wid / 2, r = lane >> 2, q = lane & 3;

#pragma unroll
    for (int mf = 0; mf < 4; mf++)
#pragma unroll
        for (int nf = 0; nf < 4; nf++) {
            int col = bcol + wn * 32 + nf * 8 + q * 2;
            float2 bb = *reinterpret_cast<const float2*>(&bias[col]);
#pragma unroll
            for (int rr = 0; rr < 2; rr++) {
                int row = brow + wm * 64 + mf * 16 + r + rr * 8;
                float v0 = acc[mf][nf][rr * 2 + 0] + bb.x;
                float v1 = acc[mf][nf][rr * 2 + 1] + bb.y;
                *reinterpret_cast<float2*>(&out[(size_t)row * DIMC + col]) = make_float2(v0, v1);
            }
        }
}

// ============================================================================
extern "C" void kernel_launch(void* const* d_in, const int* in_sizes, int n_in,
                              void* d_out, int out_size) {
    (void)in_sizes; (void)n_in; (void)out_size;
    const float* x        = (const float*)d_in[0];
    const float* w_qkv    = (const float*)d_in[1];
    const float* w_proj   = (const float*)d_in[2];
    const float* b_proj   = (const float*)d_in[3];
    const float* att_mask = (const float*)d_in[4];
    float* out = (float*)d_out;

    const int GEMM_SMEM  = (4 * 128 * LDH) * (int)sizeof(__half);      // 98304
    const int FLASH_SMEM = 3 * STAGE_H * (int)sizeof(__half);          // 61440

    cudaFuncSetAttribute(qkv_tc,   cudaFuncAttributeMaxDynamicSharedMemorySize, GEMM_SMEM);
    cudaFuncSetAttribute(proj_tc,  cudaFuncAttributeMaxDynamicSharedMemorySize, GEMM_SMEM);
    cudaFuncSetAttribute(flash_tc, cudaFuncAttributeMaxDynamicSharedMemorySize, FLASH_SMEM);

    round_all<<<NB_X + NB_WQ + NB_WP, 256>>>(x, w_qkv, w_proj);
    presig   <<<(NHEADS * SEQ * SEQ) / 1024, 256>>>(att_mask);

    qkv_tc  <<<dim3(2304 / 128, MROWS / 128), 256, GEMM_SMEM>>>();
    flash_tc<<<dim3(PAIRS, SEQ / 128), 256, FLASH_SMEM>>>();
    proj_tc <<<dim3(DIMC / 128, MROWS / 128), 256, GEMM_SMEM>>>(b_proj, out);
}

// round 16
// speedup vs baseline: 1.8096x; 1.0090x over previous
#include <cuda_runtime.h>
#include <cuda_fp16.h>
#include <cstdint>
#include <math.h>

#define DIMC   768
#define NHEADS 12
#define HDIM   64
#define BATCH  8
#define SEQ    1024
#define MROWS  (BATCH*SEQ)
#define PAIRS  (BATCH*NHEADS)
#define ATT_SCALE 0.125f

// ---------------- scratch (static device memory; no cudaMalloc allowed) ----
__device__ __align__(16) __half g_Qh [(size_t)PAIRS*SEQ*HDIM];
__device__ __align__(16) __half g_Kh [(size_t)PAIRS*SEQ*HDIM];
__device__ __align__(16) __half g_Vh [(size_t)PAIRS*SEQ*HDIM];
__device__ __align__(16) __half g_Oh [(size_t)MROWS*DIMC];
__device__ __align__(16) __half g_Xh [(size_t)MROWS*DIMC];
__device__ __align__(16) __half g_Wqh[(size_t)3*DIMC*DIMC];
__device__ __align__(16) __half g_Wph[(size_t)DIMC*DIMC];
__device__ __align__(16) __half g_Msigh[(size_t)NHEADS*SEQ*SEQ];  // fp16 gate

// ======================= helpers ===========================================
__device__ __forceinline__ int sig32h(int k) {
    return ((k & 7) >> 1) * 8 + ((k >> 4) & 1) * 4 + (k & 1) + ((k >> 3) & 1) * 2;
}
__device__ __forceinline__ void mma_f16(float (&c)[4], const uint32_t (&a)[4],
                                        uint32_t b0, uint32_t b1) {
    asm volatile("mma.sync.aligned.m16n8k16.row.col.f32.f16.f16.f32 "
                 "{%0,%1,%2,%3}, {%4,%5,%6,%7}, {%8,%9}, {%0,%1,%2,%3};"
                 : "+f"(c[0]), "+f"(c[1]), "+f"(c[2]), "+f"(c[3])
                 : "r"(a[0]), "r"(a[1]), "r"(a[2]), "r"(a[3]),
                   "r"(b0), "r"(b1));
}
__device__ __forceinline__ uint32_t h2u(__half2 h) {
    uint32_t u; *reinterpret_cast<__half2*>(&u) = h; return u;
}
__device__ __forceinline__ uint32_t smem_u32(const void* p) {
    uint32_t a;
    asm("{ .reg .u64 t; cvta.to.shared.u64 t, %1; cvt.u32.u64 %0, t; }"
        : "=r"(a) : "l"(p));
    return a;
}
#define CP_ASYNC16(dst, src) \
    asm volatile("cp.async.cg.shared.global [%0], [%1], 16;" \
                 :: "r"(dst), "l"(src) : "memory")
#define CP_COMMIT() asm volatile("cp.async.commit_group;" ::: "memory")
#define CP_WAIT(n)  asm volatile("cp.async.wait_group %0;" :: "n"(n) : "memory")

// ============================================================================
// Pre-kernels
// ============================================================================
#define NB_X  (MROWS * DIMC / 1024)
#define NB_WQ (3 * DIMC * DIMC / 1024)
#define NB_WP (DIMC * DIMC / 1024)

__device__ __forceinline__ void round_perm_h(const float* __restrict__ src,
                                             __half* __restrict__ dst,
                                             size_t i) {
    float4 v = *reinterpret_cast<const float4*>(src + i);
    int col = (int)(i % DIMC);
    size_t rowbase = i - col;
    int blk = col & ~31;
    int p0 = sig32h(col & 31);
    __half* base = dst + rowbase + blk;
    *reinterpret_cast<__half2*>(base + p0)     = __floats2half2_rn(v.x, v.y);
    *reinterpret_cast<__half2*>(base + p0 + 8) = __floats2half2_rn(v.z, v.w);
}

__global__ __launch_bounds__(256) void round_all(const float* __restrict__ x,
                                                 const float* __restrict__ wq,
                                                 const float* __restrict__ wp) {
    int blk = blockIdx.x;
    if (blk < NB_X) {
        round_perm_h(x, g_Xh, ((size_t)blk * 256 + threadIdx.x) * 4);
    } else if (blk < NB_X + NB_WQ) {
        round_perm_h(wq, g_Wqh, ((size_t)(blk - NB_X) * 256 + threadIdx.x) * 4);
    } else {
        round_perm_h(wp, g_Wph, ((size_t)(blk - NB_X - NB_WQ) * 256 + threadIdx.x) * 4);
    }
}

__global__ __launch_bounds__(256) void presig(const float* __restrict__ m) {
    size_t i = ((size_t)blockIdx.x * 256 + threadIdx.x) * 4;
    float4 v = *reinterpret_cast<const float4*>(m + i);
    __half2 a = __floats2half2_rn(ATT_SCALE / (1.f + __expf(-v.x)),
                                  ATT_SCALE / (1.f + __expf(-v.y)));
    __half2 c = __floats2half2_rn(ATT_SCALE / (1.f + __expf(-v.z)),
                                  ATT_SCALE / (1.f + __expf(-v.w)));
    uint2 u = make_uint2(h2u(a), h2u(c));
    *reinterpret_cast<uint2*>(g_Msigh + i) = u;
}

// ============================================================================
// fp16 NT GEMM core (unchanged from R15)
// ============================================================================
#define LDH 96

template <int BN, int NC, int MF, int NF, int WMDIV>
__device__ __forceinline__ void gemm_core_h(const __half* __restrict__ A, int lda,
                                            const __half* __restrict__ B, int ldb,
                                            float (&acc)[MF][NF][4],
                                            __half* smem) {
    __half* As[2] = { smem, smem + 128 * LDH };
    __half* Bs[2] = { smem + 2 * 128 * LDH, smem + 2 * 128 * LDH + BN * LDH };

    const int tid  = threadIdx.x;
    const int lane = tid & 31;
    const int wid  = tid >> 5;
    const int wm   = wid % WMDIV;
    const int wn   = wid / WMDIV;
    const int mrow0 = wm * (MF * 16);
    const int ncol0 = wn * (NF * 8);
    const int r = lane >> 2, q = lane & 3;

#pragma unroll
    for (int mf = 0; mf < MF; mf++)
#pragma unroll
        for (int nf = 0; nf < NF; nf++)
#pragma unroll
            for (int i = 0; i < 4; i++) acc[mf][nf][i] = 0.f;

    const int arow = tid >> 3, ac = (tid & 7) * 8;

    auto copy = [&](int i, int buf) {
        int k0 = i * 64;
#pragma unroll
        for (int p = 0; p < 4; p++) {
            int row = arow + p * 32;
            CP_ASYNC16(smem_u32(&As[buf][row * LDH + ac]),
                       A + (size_t)row * lda + k0 + ac);
        }
#pragma unroll
        for (int p = 0; p < BN / 32; p++) {
            int row = arow + p * 32;
            CP_ASYNC16(smem_u32(&Bs[buf][row * LDH + ac]),
                       B + (size_t)row * ldb + k0 + ac);
        }
    };

    copy(0, 0); CP_COMMIT();
    copy(1, 1); CP_COMMIT();
    CP_WAIT(1);
    __syncthreads();

#pragma unroll 1
    for (int i = 0; i < NC; i++) {
        const int buf = i & 1;
        const __half* Ab = As[buf];
        const __half* Bb = Bs[buf];
#pragma unroll
        for (int blk2 = 0; blk2 < 2; blk2++) {
            uint32_t af[MF][2][4];
            uint32_t bf[NF][2][2];
#pragma unroll
            for (int mf = 0; mf < MF; mf++) {
                const __half* ap = &Ab[(mrow0 + mf * 16 + r) * LDH + blk2 * 32 + q * 8];
                uint4 u0 = *reinterpret_cast<const uint4*>(ap);
                uint4 u1 = *reinterpret_cast<const uint4*>(ap + 8 * LDH);
                af[mf][0][0] = u0.x; af[mf][0][2] = u0.y;
                af[mf][0][1] = u1.x; af[mf][0][3] = u1.y;
                af[mf][1][0] = u0.z; af[mf][1][2] = u0.w;
                af[mf][1][1] = u1.z; af[mf][1][3] = u1.w;
            }
#pragma unroll
            for (int nf = 0; nf < NF; nf++) {
                uint4 bv = *reinterpret_cast<const uint4*>(
                    &Bb[(ncol0 + nf * 8 + r) * LDH + blk2 * 32 + q * 8]);
                bf[nf][0][0] = bv.x; bf[nf][0][1] = bv.y;
                bf[nf][1][0] = bv.z; bf[nf][1][1] = bv.w;
            }
#pragma unroll
            for (int mf = 0; mf < MF; mf++)
#pragma unroll
                for (int nf = 0; nf < NF; nf++) {
                    mma_f16(acc[mf][nf], af[mf][0], bf[nf][0][0], bf[nf][0][1]);
                    mma_f16(acc[mf][nf], af[mf][1], bf[nf][1][0], bf[nf][1][1]);
                }
        }
        if (i == NC - 1) break;
        __syncthreads();
        if (i + 2 < NC) { copy(i + 2, buf); CP_COMMIT(); CP_WAIT(1); }
        else            { CP_WAIT(0); }
        __syncthreads();
    }
}

// ============================================================================
// Kernel 1: QKV projection (fp16 core) + scatter (unchanged from R15)
// ============================================================================
__global__ __launch_bounds__(256, 2) void qkv_tc() {
    extern __shared__ __half smh[];
    float acc[4][4][4];
    int brow = blockIdx.y * 128, bcol = blockIdx.x * 128;
    gemm_core_h<128, 12, 4, 4, 2>(g_Xh + (size_t)brow * DIMC, DIMC,
                                  g_Wqh + (size_t)bcol * DIMC, DIMC, acc, smh);
    int lane = threadIdx.x & 31, wid = threadIdx.x >> 5;
    int wm = wid % 2, wn = wid / 2, r = lane >> 2, q = lane & 3;
    int part = bcol / 768, rem0 = bcol - part * 768;

#pragma unroll
    for (int mf = 0; mf < 4; mf++)
#pragma unroll
        for (int nf = 0; nf < 4; nf++) {
            int col = rem0 + wn * 32 + nf * 8 + 2 * q;
            int h = col >> 6, d = col & 63;
#pragma unroll
            for (int rr = 0; rr < 2; rr++) {
                int m = brow + wm * 64 + mf * 16 + r + rr * 8;
                int b = m >> 10, nq = m & 1023;
                float v0 = acc[mf][nf][rr * 2 + 0];
                float v1 = acc[mf][nf][rr * 2 + 1];
                int pairIdx = b * NHEADS + h;
                if (part < 2) {
                    __half* dst = (part == 0) ? g_Qh : g_Kh;
                    int blk = d & ~31, kk = d & 31;
                    int pos = sig32h(kk);
                    size_t base = ((size_t)pairIdx * SEQ + nq) * HDIM + blk + pos;
                    *reinterpret_cast<__half2*>(dst + base) = __floats2half2_rn(v0, v1);
                } else {
                    int g = nq >> 3, gp = g >> 1, hi = g & 1;
                    int qt = (nq & 7) >> 1, e = nq & 1;
                    int nfv = d >> 3, rl = d & 7;
                    size_t off = ((size_t)pairIdx * SEQ) * HDIM
                               + (size_t)gp * 1024
                               + (size_t)(nfv & 3) * 256
                               + (size_t)(rl * 4 + qt) * 8
                               + (nfv >> 2) * 4 + hi * 2 + e;
                    g_Vh[off]      = __float2half_rn(v0);
                    g_Vh[off + 32] = __float2half_rn(v1);
                }
            }
        }
}

// ============================================================================
// Kernel 2: FUSED flash attention, fp16, QROWS=256 (warp owns 32 q-rows,
// two m16 blocks) -> K/V smem reads amortized 2x. fp16 mask. 3-stage ring.
// ============================================================================
#define KT 64
#define LDHK 96
#define K_STAGE_H (64 * LDHK)
#define V_STAGE_H 4096
#define STAGE_H (K_STAGE_H + V_STAGE_H)
#define NITER (SEQ / KT)

__global__ __launch_bounds__(256, 2) void flash_tc() {
    extern __shared__ __half smh[];

    const int tid = threadIdx.x, lane = tid & 31, wid = tid >> 5;
    const int r = lane >> 2, q = lane & 3;
    const int pair = blockIdx.x;
    const int h = pair % NHEADS, b = pair / NHEADS;
    const int q0 = blockIdx.y * 256;

    const __half* Qg = g_Qh + (size_t)pair * SEQ * HDIM;
    const __half* Kg = g_Kh + (size_t)pair * SEQ * HDIM;
    const __half* Vg = g_Vh + (size_t)pair * SEQ * HDIM;
    const __half* Mgh = g_Msigh + (size_t)h * SEQ * SEQ;

    auto copyKV = [&](int kb, int buf) {
        __half* Kd = smh + buf * STAGE_H;
        __half* Vd = Kd + K_STAGE_H;
        const __half* Ksrc = Kg + (size_t)(kb * KT) * HDIM;
        const __half* Vsrc = Vg + (size_t)kb * V_STAGE_H;
#pragma unroll
        for (int p = 0; p < 2; p++) {
            int idx = tid + p * 256;
            int row = idx >> 3, c = idx & 7;
            CP_ASYNC16(smem_u32(Kd + row * LDHK + c * 8), Ksrc + row * HDIM + c * 8);
            CP_ASYNC16(smem_u32(Vd + idx * 8), Vsrc + (size_t)idx * 8);
        }
    };

    copyKV(0, 0); CP_COMMIT();
    copyKV(1, 1); CP_COMMIT();

    // ---- Q fragments for TWO m16 blocks (rows wid*32 + mb*16 + {r, r+8}) ----
    uint32_t qa[2][4][4];
#pragma unroll
    for (int mb = 0; mb < 2; mb++) {
        const __half* qr0 = Qg + (size_t)(q0 + wid * 32 + mb * 16 + r) * HDIM;
        const __half* qr1 = qr0 + 8 * HDIM;
#pragma unroll
        for (int blk = 0; blk < 2; blk++) {
            uint4 u0 = *reinterpret_cast<const uint4*>(qr0 + blk * 32 + q * 8);
            uint4 u1 = *reinterpret_cast<const uint4*>(qr1 + blk * 32 + q * 8);
            qa[mb][2 * blk][0]     = u0.x; qa[mb][2 * blk][2]     = u0.y;
            qa[mb][2 * blk][1]     = u1.x; qa[mb][2 * blk][3]     = u1.y;
            qa[mb][2 * blk + 1][0] = u0.z; qa[mb][2 * blk + 1][2] = u0.w;
            qa[mb][2 * blk + 1][1] = u1.z; qa[mb][2 * blk + 1][3] = u1.w;
        }
    }

    float od[2][8][4];
#pragma unroll
    for (int mb = 0; mb < 2; mb++)
#pragma unroll
        for (int nf = 0; nf < 8; nf++)
#pragma unroll
            for (int i = 0; i < 4; i++) od[mb][nf][i] = 0.f;
    float l00 = 0.f, l01 = 0.f, l10 = 0.f, l11 = 0.f;

    const int row_s = q0 + wid * 32 + r;
    const __half* M0 = Mgh + (size_t)row_s * SEQ + 2 * q;

#pragma unroll 1
    for (int kb = 0; kb < NITER; kb++) {
        if (kb == NITER - 1) { CP_WAIT(0); } else { CP_WAIT(1); }
        __syncthreads();
        if (kb + 2 < NITER) {
            copyKV(kb + 2, (kb + 2) % 3);
            CP_COMMIT();
        }

        const __half* Ks = smh + (kb % 3) * STAGE_H;
        const __half* Vs = Ks + K_STAGE_H;

#pragma unroll
        for (int gp = 0; gp < 4; gp++) {
            uint32_t af0[4], af1[4];
            // ---- two key-subgroups sequentially (K frags reused by both mb) --
#pragma unroll
            for (int sub = 0; sub < 2; sub++) {
                const __half* Kr = Ks + ((2 * gp + sub) * 8 + r) * LDHK;
                uint4 ka = *reinterpret_cast<const uint4*>(Kr + q * 8);
                uint4 kc = *reinterpret_cast<const uint4*>(Kr + 32 + q * 8);
                float s0[4] = {0.f, 0.f, 0.f, 0.f};
                float s1[4] = {0.f, 0.f, 0.f, 0.f};
                mma_f16(s0, qa[0][0], ka.x, ka.y);
                mma_f16(s1, qa[1][0], ka.x, ka.y);
                mma_f16(s0, qa[0][1], ka.z, ka.w);
                mma_f16(s1, qa[1][1], ka.z, ka.w);
                mma_f16(s0, qa[0][2], kc.x, kc.y);
                mma_f16(s1, qa[1][2], kc.x, kc.y);
                mma_f16(s0, qa[0][3], kc.z, kc.w);
                mma_f16(s1, qa[1][3], kc.z, kc.w);

                int col = kb * KT + gp * 16 + sub * 8;
                float2 f0 = __half22float2(*reinterpret_cast<const __half2*>(M0 + col));
                float2 f1 = __half22float2(*reinterpret_cast<const __half2*>(M0 + 8 * SEQ + col));
                float2 f2 = __half22float2(*reinterpret_cast<const __half2*>(M0 + 16 * SEQ + col));
                float2 f3 = __half22float2(*reinterpret_cast<const __half2*>(M0 + 24 * SEQ + col));

                float p00 = __expf(s0[0] * f0.x);
                float p01 = __expf(s0[1] * f0.y);
                float p02 = __expf(s0[2] * f1.x);
                float p03 = __expf(s0[3] * f1.y);
                float p10 = __expf(s1[0] * f2.x);
                float p11 = __expf(s1[1] * f2.y);
                float p12 = __expf(s1[2] * f3.x);
                float p13 = __expf(s1[3] * f3.y);
                l00 += p00 + p01; l01 += p02 + p03;
                l10 += p10 + p11; l11 += p12 + p13;

                af0[sub * 2 + 0] = h2u(__floats2half2_rn(p00, p01));
                af0[sub * 2 + 1] = h2u(__floats2half2_rn(p02, p03));
                af1[sub * 2 + 0] = h2u(__floats2half2_rn(p10, p11));
                af1[sub * 2 + 1] = h2u(__floats2half2_rn(p12, p13));
            }

            // ---- PV: V frags loaded once, used for both m-blocks ----
            const __half* Vr = Vs + gp * 1024 + lane * 8;
#pragma unroll
            for (int nfp = 0; nfp < 4; nfp++) {
                uint4 v = *reinterpret_cast<const uint4*>(Vr + nfp * 256);
                mma_f16(od[0][nfp],     af0, v.x, v.y);
                mma_f16(od[0][nfp + 4], af0, v.z, v.w);
                mma_f16(od[1][nfp],     af1, v.x, v.y);
                mma_f16(od[1][nfp + 4], af1, v.z, v.w);
            }
        }
    }

    // ---- normalize and write O (fp16, sigma32h-permuted DIMC) ----
    l00 += __shfl_xor_sync(0xffffffffu, l00, 1);
    l00 += __shfl_xor_sync(0xffffffffu, l00, 2);
    l01 += __shfl_xor_sync(0xffffffffu, l01, 1);
    l01 += __shfl_xor_sync(0xffffffffu, l01, 2);
    l10 += __shfl_xor_sync(0xffffffffu, l10, 1);
    l10 += __shfl_xor_sync(0xffffffffu, l10, 2);
    l11 += __shfl_xor_sync(0xffffffffu, l11, 1);
    l11 += __shfl_xor_sync(0xffffffffu, l11, 2);
    float inv[2][2] = { {1.f / l00, 1.f / l01}, {1.f / l10, 1.f / l11} };

#pragma unroll
    for (int mb = 0; mb < 2; mb++) {
        size_t orow0 = (size_t)b * SEQ + q0 + wid * 32 + mb * 16 + r;
#pragma unroll
        for (int nf = 0; nf < 8; nf++) {
            int d0 = nf * 8 + 2 * q;
            int colblk = h * HDIM + (d0 & ~31);
            int pos = sig32h(d0 & 31);
            *reinterpret_cast<__half2*>(&g_Oh[orow0 * DIMC + colblk + pos]) =
                __floats2half2_rn(od[mb][nf][0] * inv[mb][0], od[mb][nf][1] * inv[mb][0]);
            *reinterpret_cast<__half2*>(&g_Oh[(orow0 + 8) * DIMC + colblk + pos]) =
                __floats2half2_rn(od[mb][nf][2] * inv[mb][1], od[mb][nf][3] * inv[mb][1]);
        }
    }
}

// ============================================================================
// Kernel 3: out = O @ Wproj^T + bias (fp16 core, unchanged)
// ============================================================================
__global__ __launch_bounds__(256, 2) void proj_tc(const float* __restrict__ bias,
                                                  float* __restrict__ out) {
    extern __shared__ __half smh[];
    float acc[4][4][4];
    int brow = blockIdx.y * 128, bcol = blockIdx.x * 128;
    gemm_core_h<128, 12, 4, 4, 2>(g_Oh + (size_t)brow * DIMC, DIMC,
                                  g_Wph + (size_t)bcol * DIMC, DIMC, acc, smh);
    int lane = threadIdx.x & 31, wid = threadIdx.x >> 5;
    int wm = wid % 2, wn = wid / 2, r = lane >> 2, q = lane & 3;

#pragma unroll
    for (int mf = 0; mf < 4; mf++)
#pragma unroll
        for (int nf = 0; nf < 4; nf++) {
            int col = bcol + wn * 32 + nf * 8 + q * 2;
            float2 bb = *reinterpret_cast<const float2*>(&bias[col]);
#pragma unroll
            for (int rr = 0; rr < 2; rr++) {
                int row = brow + wm * 64 + mf * 16 + r + rr * 8;
                float v0 = acc[mf][nf][rr * 2 + 0] + bb.x;
                float v1 = acc[mf][nf][rr * 2 + 1] + bb.y;
                *reinterpret_cast<float2*>(&out[(size_t)row * DIMC + col]) = make_float2(v0, v1);
            }
        }
}

// ============================================================================
extern "C" void kernel_launch(void* const* d_in, const int* in_sizes, int n_in,
                              void* d_out, int out_size) {
    (void)in_sizes; (void)n_in; (void)out_size;
    const float* x        = (const float*)d_in[0];
    const float* w_qkv    = (const float*)d_in[1];
    const float* w_proj   = (const float*)d_in[2];
    const float* b_proj   = (const float*)d_in[3];
    const float* att_mask = (const float*)d_in[4];
    float* out = (float*)d_out;

    const int GEMM_SMEM  = (4 * 128 * LDH) * (int)sizeof(__half);
    const int FLASH_SMEM = 3 * STAGE_H * (int)sizeof(__half);

    cudaFuncSetAttribute(qkv_tc,   cudaFuncAttributeMaxDynamicSharedMemorySize, GEMM_SMEM);
    cudaFuncSetAttribute(proj_tc,  cudaFuncAttributeMaxDynamicSharedMemorySize, GEMM_SMEM);
    cudaFuncSetAttribute(flash_tc, cudaFuncAttributeMaxDynamicSharedMemorySize, FLASH_SMEM);

    round_all<<<NB_X + NB_WQ + NB_WP, 256>>>(x, w_qkv, w_proj);
    presig   <<<(NHEADS * SEQ * SEQ) / 1024, 256>>>(att_mask);

    qkv_tc  <<<dim3(2304 / 128, MROWS / 128), 256, GEMM_SMEM>>>();
    flash_tc<<<dim3(PAIRS, SEQ / 256), 256, FLASH_SMEM>>>();
    proj_tc <<<dim3(DIMC / 128, MROWS / 128), 256, GEMM_SMEM>>>(b_proj, out);
}

// round 17
// speedup vs baseline: 1.8420x; 1.0179x over previous
#include <cuda_runtime.h>
#include <cuda_fp16.h>
#include <cstdint>
#include <math.h>

#define DIMC   768
#define NHEADS 12
#define HDIM   64
#define BATCH  8
#define SEQ    1024
#define MROWS  (BATCH*SEQ)
#define PAIRS  (BATCH*NHEADS)
#define ATT_SCALE 0.125f

// ---------------- scratch (static device memory; no cudaMalloc allowed) ----
__device__ __align__(16) __half g_Qh [(size_t)PAIRS*SEQ*HDIM];
__device__ __align__(16) __half g_Kh [(size_t)PAIRS*SEQ*HDIM];
__device__ __align__(16) __half g_Vh [(size_t)PAIRS*SEQ*HDIM];
__device__ __align__(16) __half g_Oh [(size_t)MROWS*DIMC];
__device__ __align__(16) __half g_Xh [(size_t)MROWS*DIMC];
__device__ __align__(16) __half g_Wqh[(size_t)3*DIMC*DIMC];
__device__ __align__(16) __half g_Wph[(size_t)DIMC*DIMC];
__device__ __align__(16) __half g_Msigh[(size_t)NHEADS*SEQ*SEQ];

// ======================= helpers ===========================================
__device__ __forceinline__ int sig32h(int k) {
    return ((k & 7) >> 1) * 8 + ((k >> 4) & 1) * 4 + (k & 1) + ((k >> 3) & 1) * 2;
}
__device__ __forceinline__ void mma_f16(float (&c)[4], const uint32_t (&a)[4],
                                        uint32_t b0, uint32_t b1) {
    asm volatile("mma.sync.aligned.m16n8k16.row.col.f32.f16.f16.f32 "
                 "{%0,%1,%2,%3}, {%4,%5,%6,%7}, {%8,%9}, {%0,%1,%2,%3};"
                 : "+f"(c[0]), "+f"(c[1]), "+f"(c[2]), "+f"(c[3])
                 : "r"(a[0]), "r"(a[1]), "r"(a[2]), "r"(a[3]),
                   "r"(b0), "r"(b1));
}
__device__ __forceinline__ uint32_t h2u(__half2 h) {
    uint32_t u; *reinterpret_cast<__half2*>(&u) = h; return u;
}
__device__ __forceinline__ uint32_t smem_u32(const void* p) {
    uint32_t a;
    asm("{ .reg .u64 t; cvta.to.shared.u64 t, %1; cvt.u32.u64 %0, t; }"
        : "=r"(a) : "l"(p));
    return a;
}
#define CP_ASYNC16(dst, src) \
    asm volatile("cp.async.cg.shared.global [%0], [%1], 16;" \
                 :: "r"(dst), "l"(src) : "memory")
#define CP_COMMIT() asm volatile("cp.async.commit_group;" ::: "memory")
#define CP_WAIT(n)  asm volatile("cp.async.wait_group %0;" :: "n"(n) : "memory")

// ============================================================================
// Pre-kernels
// ============================================================================
#define NB_X  (MROWS * DIMC / 1024)
#define NB_WQ (3 * DIMC * DIMC / 1024)
#define NB_WP (DIMC * DIMC / 1024)

__device__ __forceinline__ void round_perm_h(const float* __restrict__ src,
                                             __half* __restrict__ dst,
                                             size_t i) {
    float4 v = *reinterpret_cast<const float4*>(src + i);
    int col = (int)(i % DIMC);
    size_t rowbase = i - col;
    int blk = col & ~31;
    int p0 = sig32h(col & 31);
    __half* base = dst + rowbase + blk;
    *reinterpret_cast<__half2*>(base + p0)     = __floats2half2_rn(v.x, v.y);
    *reinterpret_cast<__half2*>(base + p0 + 8) = __floats2half2_rn(v.z, v.w);
}

__global__ __launch_bounds__(256) void round_all(const float* __restrict__ x,
                                                 const float* __restrict__ wq,
                                                 const float* __restrict__ wp) {
    int blk = blockIdx.x;
    if (blk < NB_X) {
        round_perm_h(x, g_Xh, ((size_t)blk * 256 + threadIdx.x) * 4);
    } else if (blk < NB_X + NB_WQ) {
        round_perm_h(wq, g_Wqh, ((size_t)(blk - NB_X) * 256 + threadIdx.x) * 4);
    } else {
        round_perm_h(wp, g_Wph, ((size_t)(blk - NB_X - NB_WQ) * 256 + threadIdx.x) * 4);
    }
}

__global__ __launch_bounds__(256) void presig(const float* __restrict__ m) {
    size_t i = ((size_t)blockIdx.x * 256 + threadIdx.x) * 4;
    float4 v = *reinterpret_cast<const float4*>(m + i);
    __half2 a = __floats2half2_rn(ATT_SCALE / (1.f + __expf(-v.x)),
                                  ATT_SCALE / (1.f + __expf(-v.y)));
    __half2 c = __floats2half2_rn(ATT_SCALE / (1.f + __expf(-v.z)),
                                  ATT_SCALE / (1.f + __expf(-v.w)));
    uint2 u = make_uint2(h2u(a), h2u(c));
    *reinterpret_cast<uint2*>(g_Msigh + i) = u;
}

// ============================================================================
// fp16 NT GEMM core (unchanged from R15)
// ============================================================================
#define LDH 96

template <int BN, int NC, int MF, int NF, int WMDIV>
__device__ __forceinline__ void gemm_core_h(const __half* __restrict__ A, int lda,
                                            const __half* __restrict__ B, int ldb,
                                            float (&acc)[MF][NF][4],
                                            __half* smem) {
    __half* As[2] = { smem, smem + 128 * LDH };
    __half* Bs[2] = { smem + 2 * 128 * LDH, smem + 2 * 128 * LDH + BN * LDH };

    const int tid  = threadIdx.x;
    const int lane = tid & 31;
    const int wid  = tid >> 5;
    const int wm   = wid % WMDIV;
    const int wn   = wid / WMDIV;
    const int mrow0 = wm * (MF * 16);
    const int ncol0 = wn * (NF * 8);
    const int r = lane >> 2, q = lane & 3;

#pragma unroll
    for (int mf = 0; mf < MF; mf++)
#pragma unroll
        for (int nf = 0; nf < NF; nf++)
#pragma unroll
            for (int i = 0; i < 4; i++) acc[mf][nf][i] = 0.f;

    const int arow = tid >> 3, ac = (tid & 7) * 8;

    auto copy = [&](int i, int buf) {
        int k0 = i * 64;
#pragma unroll
        for (int p = 0; p < 4; p++) {
            int row = arow + p * 32;
            CP_ASYNC16(smem_u32(&As[buf][row * LDH + ac]),
                       A + (size_t)row * lda + k0 + ac);
        }
#pragma unroll
        for (int p = 0; p < BN / 32; p++) {
            int row = arow + p * 32;
            CP_ASYNC16(smem_u32(&Bs[buf][row * LDH + ac]),
                       B + (size_t)row * ldb + k0 + ac);
        }
    };

    copy(0, 0); CP_COMMIT();
    copy(1, 1); CP_COMMIT();
    CP_WAIT(1);
    __syncthreads();

#pragma unroll 1
    for (int i = 0; i < NC; i++) {
        const int buf = i & 1;
        const __half* Ab = As[buf];
        const __half* Bb = Bs[buf];
#pragma unroll
        for (int blk2 = 0; blk2 < 2; blk2++) {
            uint32_t af[MF][2][4];
            uint32_t bf[NF][2][2];
#pragma unroll
            for (int mf = 0; mf < MF; mf++) {
                const __half* ap = &Ab[(mrow0 + mf * 16 + r) * LDH + blk2 * 32 + q * 8];
                uint4 u0 = *reinterpret_cast<const uint4*>(ap);
                uint4 u1 = *reinterpret_cast<const uint4*>(ap + 8 * LDH);
                af[mf][0][0] = u0.x; af[mf][0][2] = u0.y;
                af[mf][0][1] = u1.x; af[mf][0][3] = u1.y;
                af[mf][1][0] = u0.z; af[mf][1][2] = u0.w;
                af[mf][1][1] = u1.z; af[mf][1][3] = u1.w;
            }
#pragma unroll
            for (int nf = 0; nf < NF; nf++) {
                uint4 bv = *reinterpret_cast<const uint4*>(
                    &Bb[(ncol0 + nf * 8 + r) * LDH + blk2 * 32 + q * 8]);
                bf[nf][0][0] = bv.x; bf[nf][0][1] = bv.y;
                bf[nf][1][0] = bv.z; bf[nf][1][1] = bv.w;
            }
#pragma unroll
            for (int mf = 0; mf < MF; mf++)
#pragma unroll
                for (int nf = 0; nf < NF; nf++) {
                    mma_f16(acc[mf][nf], af[mf][0], bf[nf][0][0], bf[nf][0][1]);
                    mma_f16(acc[mf][nf], af[mf][1], bf[nf][1][0], bf[nf][1][1]);
                }
        }
        if (i == NC - 1) break;
        __syncthreads();
        if (i + 2 < NC) { copy(i + 2, buf); CP_COMMIT(); CP_WAIT(1); }
        else            { CP_WAIT(0); }
        __syncthreads();
    }
}

// ============================================================================
// Kernel 1: QKV projection (fp16 core) + scatter (unchanged)
// ============================================================================
__global__ __launch_bounds__(256, 2) void qkv_tc() {
    extern __shared__ __half smh[];
    float acc[4][4][4];
    int brow = blockIdx.y * 128, bcol = blockIdx.x * 128;
    gemm_core_h<128, 12, 4, 4, 2>(g_Xh + (size_t)brow * DIMC, DIMC,
                                  g_Wqh + (size_t)bcol * DIMC, DIMC, acc, smh);
    int lane = threadIdx.x & 31, wid = threadIdx.x >> 5;
    int wm = wid % 2, wn = wid / 2, r = lane >> 2, q = lane & 3;
    int part = bcol / 768, rem0 = bcol - part * 768;

#pragma unroll
    for (int mf = 0; mf < 4; mf++)
#pragma unroll
        for (int nf = 0; nf < 4; nf++) {
            int col = rem0 + wn * 32 + nf * 8 + 2 * q;
            int h = col >> 6, d = col & 63;
#pragma unroll
            for (int rr = 0; rr < 2; rr++) {
                int m = brow + wm * 64 + mf * 16 + r + rr * 8;
                int b = m >> 10, nq = m & 1023;
                float v0 = acc[mf][nf][rr * 2 + 0];
                float v1 = acc[mf][nf][rr * 2 + 1];
                int pairIdx = b * NHEADS + h;
                if (part < 2) {
                    __half* dst = (part == 0) ? g_Qh : g_Kh;
                    int blk = d & ~31, kk = d & 31;
                    int pos = sig32h(kk);
                    size_t base = ((size_t)pairIdx * SEQ + nq) * HDIM + blk + pos;
                    *reinterpret_cast<__half2*>(dst + base) = __floats2half2_rn(v0, v1);
                } else {
                    int g = nq >> 3, gp = g >> 1, hi = g & 1;
                    int qt = (nq & 7) >> 1, e = nq & 1;
                    int nfv = d >> 3, rl = d & 7;
                    size_t off = ((size_t)pairIdx * SEQ) * HDIM
                               + (size_t)gp * 1024
                               + (size_t)(nfv & 3) * 256
                               + (size_t)(rl * 4 + qt) * 8
                               + (nfv >> 2) * 4 + hi * 2 + e;
                    g_Vh[off]      = __float2half_rn(v0);
                    g_Vh[off + 32] = __float2half_rn(v1);
                }
            }
        }
}

// ============================================================================
// Kernel 2: FUSED flash attention, fp16, QROWS=128 (R15 shape), fp16 mask,
// 3 CTAs/SM (85 regs: qa 16 + od 32 persistent), 3-stage cp.async ring.
// ============================================================================
#define KT 64
#define LDHK 96
#define K_STAGE_H (64 * LDHK)
#define V_STAGE_H 4096
#define STAGE_H (K_STAGE_H + V_STAGE_H)
#define NITER (SEQ / KT)

__global__ __launch_bounds__(256, 3) void flash_tc() {
    extern __shared__ __half smh[];

    const int tid = threadIdx.x, lane = tid & 31, wid = tid >> 5;
    const int r = lane >> 2, q = lane & 3;
    const int pair = blockIdx.x;
    const int h = pair % NHEADS, b = pair / NHEADS;
    const int q0 = blockIdx.y * 128;

    const __half* Qg = g_Qh + (size_t)pair * SEQ * HDIM;
    const __half* Kg = g_Kh + (size_t)pair * SEQ * HDIM;
    const __half* Vg = g_Vh + (size_t)pair * SEQ * HDIM;
    const __half* Mgh = g_Msigh + (size_t)h * SEQ * SEQ;

    auto copyKV = [&](int kb, int buf) {
        __half* Kd = smh + buf * STAGE_H;
        __half* Vd = Kd + K_STAGE_H;
        const __half* Ksrc = Kg + (size_t)(kb * KT) * HDIM;
        const __half* Vsrc = Vg + (size_t)kb * V_STAGE_H;
#pragma unroll
        for (int p = 0; p < 2; p++) {
            int idx = tid + p * 256;
            int row = idx >> 3, c = idx & 7;
            CP_ASYNC16(smem_u32(Kd + row * LDHK + c * 8), Ksrc + row * HDIM + c * 8);
            CP_ASYNC16(smem_u32(Vd + idx * 8), Vsrc + (size_t)idx * 8);
        }
    };

    copyKV(0, 0); CP_COMMIT();
    copyKV(1, 1); CP_COMMIT();

    // ---- Q fragments (16 regs) from sigma32h global ----
    uint32_t qa[4][4];
    {
        const __half* qr0 = Qg + (size_t)(q0 + wid * 16 + r) * HDIM;
        const __half* qr1 = qr0 + 8 * HDIM;
#pragma unroll
        for (int blk = 0; blk < 2; blk++) {
            uint4 u0 = *reinterpret_cast<const uint4*>(qr0 + blk * 32 + q * 8);
            uint4 u1 = *reinterpret_cast<const uint4*>(qr1 + blk * 32 + q * 8);
            qa[2 * blk][0]     = u0.x; qa[2 * blk][2]     = u0.y;
            qa[2 * blk][1]     = u1.x; qa[2 * blk][3]     = u1.y;
            qa[2 * blk + 1][0] = u0.z; qa[2 * blk + 1][2] = u0.w;
            qa[2 * blk + 1][1] = u1.z; qa[2 * blk + 1][3] = u1.w;
        }
    }

    float od[8][4];
#pragma unroll
    for (int nf = 0; nf < 8; nf++)
#pragma unroll
        for (int i = 0; i < 4; i++) od[nf][i] = 0.f;
    float l0 = 0.f, l1 = 0.f;

    const int row_s0 = q0 + wid * 16 + r;
    const __half* Mrow0 = Mgh + (size_t)row_s0 * SEQ + 2 * q;
    const __half* Mrow1 = Mrow0 + 8 * SEQ;

#pragma unroll 1
    for (int kb = 0; kb < NITER; kb++) {
        if (kb == NITER - 1) { CP_WAIT(0); } else { CP_WAIT(1); }
        __syncthreads();
        if (kb + 2 < NITER) {
            copyKV(kb + 2, (kb + 2) % 3);
            CP_COMMIT();
        }

        const __half* Ks = smh + (kb % 3) * STAGE_H;
        const __half* Vs = Ks + K_STAGE_H;

#pragma unroll
        for (int gp = 0; gp < 4; gp++) {
            float s0a[4] = {0.f, 0.f, 0.f, 0.f};
            float s1a[4] = {0.f, 0.f, 0.f, 0.f};
            const __half* Kr0 = Ks + ((2 * gp)     * 8 + r) * LDHK;
            const __half* Kr1 = Ks + ((2 * gp + 1) * 8 + r) * LDHK;
            uint4 k00 = *reinterpret_cast<const uint4*>(Kr0 + q * 8);
            uint4 k01 = *reinterpret_cast<const uint4*>(Kr0 + 32 + q * 8);
            uint4 k10 = *reinterpret_cast<const uint4*>(Kr1 + q * 8);
            uint4 k11 = *reinterpret_cast<const uint4*>(Kr1 + 32 + q * 8);
            mma_f16(s0a, qa[0], k00.x, k00.y);
            mma_f16(s1a, qa[0], k10.x, k10.y);
            mma_f16(s0a, qa[1], k00.z, k00.w);
            mma_f16(s1a, qa[1], k10.z, k10.w);
            mma_f16(s0a, qa[2], k01.x, k01.y);
            mma_f16(s1a, qa[2], k11.x, k11.y);
            mma_f16(s0a, qa[3], k01.z, k01.w);
            mma_f16(s1a, qa[3], k11.z, k11.w);

            int col0 = kb * KT + gp * 16;
            float2 m00 = __half22float2(*reinterpret_cast<const __half2*>(Mrow0 + col0));
            float2 m01 = __half22float2(*reinterpret_cast<const __half2*>(Mrow0 + col0 + 8));
            float2 m10 = __half22float2(*reinterpret_cast<const __half2*>(Mrow1 + col0));
            float2 m11 = __half22float2(*reinterpret_cast<const __half2*>(Mrow1 + col0 + 8));

            float p0c0 = __expf(s0a[0] * m00.x);
            float p0c1 = __expf(s0a[1] * m00.y);
            float p0c2 = __expf(s0a[2] * m10.x);
            float p0c3 = __expf(s0a[3] * m10.y);
            float p1c0 = __expf(s1a[0] * m01.x);
            float p1c1 = __expf(s1a[1] * m01.y);
            float p1c2 = __expf(s1a[2] * m11.x);
            float p1c3 = __expf(s1a[3] * m11.y);
            l0 += p0c0 + p0c1 + p1c0 + p1c1;
            l1 += p0c2 + p0c3 + p1c2 + p1c3;

            uint32_t af[4];
            af[0] = h2u(__floats2half2_rn(p0c0, p0c1));
            af[1] = h2u(__floats2half2_rn(p0c2, p0c3));
            af[2] = h2u(__floats2half2_rn(p1c0, p1c1));
            af[3] = h2u(__floats2half2_rn(p1c2, p1c3));

            const __half* Vr = Vs + gp * 1024 + lane * 8;
#pragma unroll
            for (int nfp = 0; nfp < 4; nfp++) {
                uint4 v = *reinterpret_cast<const uint4*>(Vr + nfp * 256);
                mma_f16(od[nfp],     af, v.x, v.y);
                mma_f16(od[nfp + 4], af, v.z, v.w);
            }
        }
    }

    // ---- normalize and write O (fp16, sigma32h-permuted DIMC) ----
    l0 += __shfl_xor_sync(0xffffffffu, l0, 1);
    l0 += __shfl_xor_sync(0xffffffffu, l0, 2);
    l1 += __shfl_xor_sync(0xffffffffu, l1, 1);
    l1 += __shfl_xor_sync(0xffffffffu, l1, 2);
    float inv0 = 1.f / l0, inv1 = 1.f / l1;

    size_t orow0 = (size_t)b * SEQ + q0 + wid * 16 + r;
#pragma unroll
    for (int nf = 0; nf < 8; nf++) {
        int d0 = nf * 8 + 2 * q;
        int colblk = h * HDIM + (d0 & ~31);
        int pos = sig32h(d0 & 31);
        *reinterpret_cast<__half2*>(&g_Oh[orow0 * DIMC + colblk + pos]) =
            __floats2half2_rn(od[nf][0] * inv0, od[nf][1] * inv0);
        *reinterpret_cast<__half2*>(&g_Oh[(orow0 + 8) * DIMC + colblk + pos]) =
            __floats2half2_rn(od[nf][2] * inv1, od[nf][3] * inv1);
    }
}

// ============================================================================
// Kernel 3: out = O @ Wproj^T + bias (fp16 core, unchanged)
// ============================================================================
__global__ __launch_bounds__(256, 2) void proj_tc(const float* __restrict__ bias,
                                                  float* __restrict__ out) {
    extern __shared__ __half smh[];
    float acc[4][4][4];
    int brow = blockIdx.y * 128, bcol = blockIdx.x * 128;
    gemm_core_h<128, 12, 4, 4, 2>(g_Oh + (size_t)brow * DIMC, DIMC,
                                  g_Wph + (size_t)bcol * DIMC, DIMC, acc, smh);
    int lane = threadIdx.x & 31, wid = threadIdx.x >> 5;
    int wm = wid % 2, wn = wid / 2, r = lane >> 2, q = lane & 3;

#pragma unroll
    for (int mf = 0; mf < 4; mf++)
#pragma unroll
        for (int nf = 0; nf < 4; nf++) {
            int col = bcol + wn * 32 + nf * 8 + q * 2;
            float2 bb = *reinterpret_cast<const float2*>(&bias[col]);
#pragma unroll
            for (int rr = 0; rr < 2; rr++) {
                int row = brow + wm * 64 + mf * 16 + r + rr * 8;
                float v0 = acc[mf][nf][rr * 2 + 0] + bb.x;
                float v1 = acc[mf][nf][rr * 2 + 1] + bb.y;
                *reinterpret_cast<float2*>(&out[(size_t)row * DIMC + col]) = make_float2(v0, v1);
            }
        }
}

// ============================================================================
extern "C" void kernel_launch(void* const* d_in, const int* in_sizes, int n_in,
                              void* d_out, int out_size) {
    (void)in_sizes; (void)n_in; (void)out_size;
    const float* x        = (const float*)d_in[0];
    const float* w_qkv    = (const float*)d_in[1];
    const float* w_proj   = (const float*)d_in[2];
    const float* b_proj   = (const float*)d_in[3];
    const float* att_mask = (const float*)d_in[4];
    float* out = (float*)d_out;

    const int GEMM_SMEM  = (4 * 128 * LDH) * (int)sizeof(__half);
    const int FLASH_SMEM = 3 * STAGE_H * (int)sizeof(__half);      // 61440

    cudaFuncSetAttribute(qkv_tc,   cudaFuncAttributeMaxDynamicSharedMemorySize, GEMM_SMEM);
    cudaFuncSetAttribute(proj_tc,  cudaFuncAttributeMaxDynamicSharedMemorySize, GEMM_SMEM);
    cudaFuncSetAttribute(flash_tc, cudaFuncAttributeMaxDynamicSharedMemorySize, FLASH_SMEM);

    round_all<<<NB_X + NB_WQ + NB_WP, 256>>>(x, w_qkv, w_proj);
    presig   <<<(NHEADS * SEQ * SEQ) / 1024, 256>>>(att_mask);

    qkv_tc  <<<dim3(2304 / 128, MROWS / 128), 256, GEMM_SMEM>>>();
    flash_tc<<<dim3(PAIRS, SEQ / 128), 256, FLASH_SMEM>>>();
    proj_tc <<<dim3(DIMC / 128, MROWS / 128), 256, GEMM_SMEM>>>(b_proj, out);
}